// round 12
// baseline (speedup 1.0000x reference)
#include <cuda_runtime.h>

#define TT    512
#define BSZ   256
#define DIN   64
#define HH    128
#define BPC   8
#define NGRP  32
#define NTHR  512
#define RPC   256        // rows per CTA: 4 gates x 64 units
#define UPC   64
#define NB0   48         // k-blocks layer0 (K=192), permuted [x16|own8..|peer16]
#define NB1   64         // k-blocks layer1 (K=256), permuted [h0 32|own16|peer16]
#define NCTA  (NGRP*4)   // 128
#define DYNSMEM (NB0*RPC*16)   // 192 KB

// Blocked weights, k-columns PERMUTED per half (dependency order):
// L0 half: k_new<64: x(k_new); <128: h0 own unit half*64+(k_new-64);
//          else: h0 peer unit (1-half)*64+(k_new-128)
// L1 half: k_new<128: h0(k_new); <192: h1 own; else h1 peer
__device__ float4 g_W0B[2 * NB0 * RPC];
__device__ float4 g_W1B[2 * NB1 * RPC];

__global__ void prep_kernel(const float* __restrict__ Wih0,
                            const float* __restrict__ Whh0,
                            const float* __restrict__ Wih1,
                            const float* __restrict__ Whh1)
{
    int idx = blockIdx.x * blockDim.x + threadIdx.x;
    int stride = gridDim.x * blockDim.x;
    for (int e = idx; e < 2 * NB0 * RPC * 4; e += stride) {
        int i = e & 3, e2 = e >> 2;
        int r = e2 % RPC, e3 = e2 / RPC;
        int kb = e3 % NB0, half = e3 / NB0;
        int kn = kb * 4 + i;
        int ko = (kn < 64) ? kn
               : (kn < 128) ? 64 + half * 64 + (kn - 64)
                            : 64 + (1 - half) * 64 + (kn - 128);
        int gate = r >> 6, ul = r & 63;
        int grow = gate * HH + half * UPC + ul;
        float v = (ko < DIN) ? Wih0[grow * DIN + ko] : Whh0[grow * HH + (ko - DIN)];
        ((float*)g_W0B)[e] = v;
    }
    for (int e = idx; e < 2 * NB1 * RPC * 4; e += stride) {
        int i = e & 3, e2 = e >> 2;
        int r = e2 % RPC, e3 = e2 / RPC;
        int kb = e3 % NB1, half = e3 / NB1;
        int kn = kb * 4 + i;
        int ko = (kn < 128) ? kn
               : (kn < 192) ? 128 + half * 64 + (kn - 128)
                            : 128 + (1 - half) * 64 + (kn - 192);
        int gate = r >> 6, ul = r & 63;
        int grow = gate * HH + half * UPC + ul;
        float v = (ko < HH) ? Wih1[grow * HH + ko] : Whh1[grow * HH + (ko - HH)];
        ((float*)g_W1B)[e] = v;
    }
}

__device__ __forceinline__ void fma2(unsigned long long& d,
                                     unsigned long long a,
                                     unsigned long long b)
{
    asm("fma.rn.f32x2 %0, %1, %2, %0;" : "+l"(d) : "l"(a), "l"(b));
}
__device__ __forceinline__ float flo(unsigned long long v) {
    return __uint_as_float((unsigned)(v & 0xffffffffu));
}
__device__ __forceinline__ float fhi(unsigned long long v) {
    return __uint_as_float((unsigned)(v >> 32));
}
__device__ __forceinline__ float sigf(float x) {
    return __fdividef(1.0f, 1.0f + __expf(-x));
}
__device__ __forceinline__ float tanhfast(float x) {
    return 1.0f - __fdividef(2.0f, __expf(2.0f * x) + 1.0f);
}
__device__ __forceinline__ float ldcg(const float* p) {
    float v;
    asm volatile("ld.global.cg.f32 %0, [%1];" : "=f"(v) : "l"(p) : "memory");
    return v;
}
__device__ __forceinline__ ulonglong2 ldcg_u2(const ulonglong2* p) {
    ulonglong2 v;
    asm volatile("ld.global.cg.v2.u64 {%0,%1}, [%2];"
                 : "=l"(v.x), "=l"(v.y) : "l"(p) : "memory");
    return v;
}
__device__ __forceinline__ unsigned smem_u32(const void* p) {
    unsigned a;
    asm("{ .reg .u64 t; cvta.to.shared.u64 t, %1; cvt.u32.u64 %0, t; }"
        : "=r"(a) : "l"(p));
    return a;
}
__device__ __forceinline__ unsigned cta_rank() {
    unsigned r;
    asm("mov.u32 %0, %%cluster_ctarank;" : "=r"(r));
    return r;
}
__device__ __forceinline__ unsigned mapa_u32(unsigned a, unsigned rank) {
    unsigned r;
    asm("mapa.shared::cluster.u32 %0, %1, %2;" : "=r"(r) : "r"(a), "r"(rank));
    return r;
}
__device__ __forceinline__ void mbar_init(unsigned a, unsigned cnt) {
    asm volatile("mbarrier.init.shared.b64 [%0], %1;" :: "r"(a), "r"(cnt) : "memory");
}
__device__ __forceinline__ void fence_cluster() {
    asm volatile("fence.acq_rel.cluster;" ::: "memory");
}
__device__ __forceinline__ void mbar_arrive_rk(unsigned local_a, unsigned rank) {
    unsigned ra = mapa_u32(local_a, rank);
    asm volatile("mbarrier.arrive.release.cluster.shared::cluster.b64 _, [%0];"
                 :: "r"(ra) : "memory");
}
__device__ __forceinline__ void mbar_wait(unsigned a, unsigned parity) {
    asm volatile(
        "{\n\t.reg .pred P;\n\t"
        "W_%=:\n\t"
        "mbarrier.try_wait.parity.acquire.cluster.shared::cta.b64 P, [%0], %1, 0x989680;\n\t"
        "@P bra D_%=;\n\t"
        "bra W_%=;\n\t"
        "D_%=:\n\t}"
        :: "r"(a), "r"(parity) : "memory");
}
__device__ __forceinline__ void st_dsmem(unsigned local_a, unsigned rank, float v) {
    unsigned ra = mapa_u32(local_a, rank);
    asm volatile("st.shared::cluster.f32 [%0], %1;" :: "r"(ra), "f"(v) : "memory");
}
#define CLUSTER_SYNC() do { \
    asm volatile("barrier.cluster.arrive.aligned;" ::: "memory"); \
    asm volatile("barrier.cluster.wait.aligned;" ::: "memory"); \
} while (0)

// accumulate one k-block (16B of w) against 8 batches
__device__ __forceinline__ void acc8(unsigned long long* acc, ulonglong2 w,
                                     const float* xb, int kb)
{
    #pragma unroll
    for (int b = 0; b < BPC; ++b) {
        ulonglong2 xv = ((const ulonglong2*)(xb + (size_t)b * 256))[kb];
        fma2(acc[b], w.x, xv.x);
        fma2(acc[b], w.y, xv.y);
    }
}

__global__ void __launch_bounds__(NTHR, 1) __cluster_dims__(4, 1, 1)
lstm_kernel(const float* __restrict__ state,
            const float* __restrict__ b_ih0, const float* __restrict__ b_hh0,
            const float* __restrict__ b_ih1, const float* __restrict__ b_hh1,
            const float* __restrict__ W_out, const float* __restrict__ b_out,
            float* __restrict__ out)
{
    extern __shared__ __align__(16) ulonglong2 ws[];   // resident weights

    // rows of 256 floats; L0: [x64|own h0|peer h0|pad], L1: [h0 128|own h1|peer h1]
    __shared__ __align__(16) float ubuf[2][BPC][256];
    __shared__ float sg[BPC][2][RPC];
    __shared__ float swout[HH];
    __shared__ float sbout;
    __shared__ __align__(8) unsigned long long mbar[6];
    // L0: 0/1=P_full(c1)  2/3=P_empty(c1)  4/5=L1_empty(c2)
    // L1: 0/1=H_full(c2)  2/3=Q_full(c1)   4/5=Q_empty(c1)

    const int grp  = blockIdx.x >> 2;
    const int gb   = grp * BPC;
    const unsigned rank = cta_rank();
    const int tid  = threadIdx.x;
    const int seg  = tid >> 8;
    const int r    = tid & 255;
    const int ua   = tid & 63;
    const int ba   = tid >> 6 & 7;
    const unsigned mb = smem_u32(&mbar[0]);

    if (tid == 0) {
        unsigned cA = (rank < 2) ? 1u : 2u;   // full-A count
        unsigned cE = (rank < 2) ? 2u : 1u;   // empty count (idx4/5)
        mbar_init(mb + 0,  cA); mbar_init(mb + 8,  cA);
        mbar_init(mb + 16, 1);  mbar_init(mb + 24, 1);
        mbar_init(mb + 32, cE); mbar_init(mb + 40, cE);
    }

    if (rank < 2) {
        // =================== L0 half-CTA ===================
        const int half = rank;
        const unsigned peer = rank ^ 1u;
        {
            const ulonglong2* src = (const ulonglong2*)g_W0B + (size_t)half * NB0 * RPC;
            for (int e = tid; e < NB0 * RPC; e += NTHR) ws[e] = ldcg_u2(src + e);
        }
        const int gr0 = half * UPC + ua;
        const float bi = b_ih0[gr0]        + b_hh0[gr0];
        const float bf = b_ih0[HH+gr0]     + b_hh0[HH+gr0];
        const float bg = b_ih0[2*HH+gr0]   + b_hh0[2*HH+gr0];
        const float bo = b_ih0[3*HH+gr0]   + b_hh0[3*HH+gr0];
        ubuf[0][ba][64 + ua]  = 0.0f;               // own h0(-1)
        ubuf[0][ba][128 + ua] = 0.0f;               // peer h0(-1)
        ubuf[0][ba][ua] = ldcg(state + (gb + ba) * DIN + ua);   // x(0)
        float cst = 0.0f;
        int pf[2] = {0,0}, pe[2] = {0,0}, ple[2] = {0,0};
        __syncthreads();
        CLUSTER_SYNC();

        for (int t = 0; t < TT; ++t) {
            const int q = t & 1;
            float xr = 0.0f;
            if (t + 1 < TT)
                xr = ldcg(state + ((size_t)(t + 1) * BSZ + gb + ba) * DIN + ua);

            unsigned long long acc[BPC];
            #pragma unroll
            for (int b = 0; b < BPC; ++b) acc[b] = 0ull;
            const float* xb = &ubuf[q][0][0];
            if (seg == 0) {
                #pragma unroll 4
                for (int kb = 0; kb < 24; ++kb) acc8(acc, ws[kb * RPC + r], xb, kb);
            } else {
                #pragma unroll 4
                for (int kb = 24; kb < 32; ++kb) acc8(acc, ws[kb * RPC + r], xb, kb);
                if (t > 0) mbar_wait(mb + (unsigned)q * 8, (unsigned)pf[q]);
                #pragma unroll 4
                for (int kb = 32; kb < 48; ++kb) acc8(acc, ws[kb * RPC + r], xb, kb);
            }
            if (t > 0) pf[q] ^= 1;
            #pragma unroll
            for (int b = 0; b < BPC; ++b)
                sg[b][seg][r] = flo(acc[b]) + fhi(acc[b]);
            __syncthreads();   // B2
            if (tid == 0) {
                fence_cluster();
                mbar_arrive_rk(mb + 16 + (unsigned)q * 8, peer);   // P_empty[q] -> peer
            }
            if (t >= 1) { mbar_wait(mb + 16 + (unsigned)(q^1) * 8, (unsigned)pe[q^1]); pe[q^1] ^= 1; }
            if (t >= 2) { mbar_wait(mb + 32 + (unsigned)q * 8, (unsigned)ple[q]); ple[q] ^= 1; }

            {   // act
                float p0 = sg[ba][0][ua]        + sg[ba][1][ua]        + bi;
                float p1 = sg[ba][0][64+ua]     + sg[ba][1][64+ua]     + bf;
                float p2 = sg[ba][0][128+ua]    + sg[ba][1][128+ua]    + bg;
                float p3 = sg[ba][0][192+ua]    + sg[ba][1][192+ua]    + bo;
                float gi = sigf(p0), gf = sigf(p1);
                float gG = tanhfast(p2), go = sigf(p3);
                cst = gf * cst + gi * gG;
                float h = go * tanhfast(cst);
                ubuf[q ^ 1][ba][64 + ua] = h;                                 // own
                st_dsmem(smem_u32(&ubuf[q ^ 1][ba][128 + ua]), peer, h);      // peer L0
                unsigned l1a = smem_u32(&ubuf[q][ba][half * 64 + ua]);
                st_dsmem(l1a, 2u, h);                                         // L1a
                st_dsmem(l1a, 3u, h);                                         // L1b
                ubuf[q ^ 1][ba][ua] = xr;                                     // x(t+1)
            }
            __syncthreads();   // B3
            if (tid == 0) {
                fence_cluster();
                mbar_arrive_rk(mb + (unsigned)(q^1) * 8, peer);   // P_full[q^1]
                mbar_arrive_rk(mb + (unsigned)q * 8, 2u);         // H_full[q]
                mbar_arrive_rk(mb + (unsigned)q * 8, 3u);
            }
        }
        CLUSTER_SYNC();
    } else {
        // =================== L1 half-CTA ===================
        const int half = rank - 2;
        const unsigned peer = rank ^ 1u;
        {   // smem weights: kb 8..31 -> ws[0..24), kb 40..63 -> ws[24..48)
            const ulonglong2* src = (const ulonglong2*)g_W1B + (size_t)half * NB1 * RPC;
            for (int e = tid; e < NB0 * RPC; e += NTHR) {
                int idx = e >> 8, rr = e & 255;
                int kbn = (idx < 24) ? (8 + idx) : (16 + idx);
                ws[e] = ldcg_u2(src + ((size_t)kbn * RPC + rr));
            }
        }
        const ulonglong2* wg0 = (const ulonglong2*)g_W1B + (size_t)half * NB1 * RPC + r;          // kb 0..7
        const ulonglong2* wg1 = (const ulonglong2*)g_W1B + ((size_t)half * NB1 + 32) * RPC + r;   // kb 32..39
        const int gr0 = half * UPC + ua;
        const float bi = b_ih1[gr0]        + b_hh1[gr0];
        const float bf = b_ih1[HH+gr0]     + b_hh1[HH+gr0];
        const float bg = b_ih1[2*HH+gr0]   + b_hh1[2*HH+gr0];
        const float bo = b_ih1[3*HH+gr0]   + b_hh1[3*HH+gr0];
        if (rank == 2) {
            if (tid < HH) swout[tid] = W_out[tid];
            if (tid == 0) sbout = b_out[0];
        }
        ubuf[0][ba][128 + ua] = 0.0f;   // own h1(-1)
        ubuf[0][ba][192 + ua] = 0.0f;   // peer h1(-1)
        float cst = 0.0f;
        int ph[2] = {0,0}, pqf[2] = {0,0}, pqe[2] = {0,0};
        __syncthreads();
        CLUSTER_SYNC();

        for (int t = 0; t < TT; ++t) {
            const int q = t & 1;
            unsigned long long acc[BPC];
            #pragma unroll
            for (int b = 0; b < BPC; ++b) acc[b] = 0ull;
            const float* xb = &ubuf[q][0][0];
            if (seg == 0) {
                mbar_wait(mb + (unsigned)q * 8, (unsigned)ph[q]);   // H_full
                #pragma unroll
                for (int kb = 0; kb < 8; ++kb) acc8(acc, ldcg_u2(wg0 + (size_t)kb * RPC), xb, kb);
                #pragma unroll 4
                for (int kb = 8; kb < 32; ++kb) acc8(acc, ws[(kb - 8) * RPC + r], xb, kb);
            } else {
                #pragma unroll
                for (int kb = 32; kb < 40; ++kb) acc8(acc, ldcg_u2(wg1 + (size_t)(kb - 32) * RPC), xb, kb);
                #pragma unroll 4
                for (int kb = 40; kb < 48; ++kb) acc8(acc, ws[(kb - 16) * RPC + r], xb, kb);
                if (t > 0) mbar_wait(mb + 16 + (unsigned)q * 8, (unsigned)pqf[q]);  // Q_full
                #pragma unroll 4
                for (int kb = 48; kb < 64; ++kb) acc8(acc, ws[(kb - 16) * RPC + r], xb, kb);
            }
            ph[q] ^= 1;
            if (t > 0) pqf[q] ^= 1;
            #pragma unroll
            for (int b = 0; b < BPC; ++b)
                sg[b][seg][r] = flo(acc[b]) + fhi(acc[b]);
            __syncthreads();   // B2
            if (tid == 0) {
                fence_cluster();
                mbar_arrive_rk(mb + 32 + (unsigned)q * 8, 0u);     // L1_empty[q]
                mbar_arrive_rk(mb + 32 + (unsigned)q * 8, 1u);
                mbar_arrive_rk(mb + 32 + (unsigned)q * 8, peer);   // Q_empty[q]
            }
            if (t >= 1) { mbar_wait(mb + 32 + (unsigned)(q^1) * 8, (unsigned)pqe[q^1]); pqe[q^1] ^= 1; }

            // head: out(t-1) from slot q h1 (rank2 only; after B2 all visible)
            if (rank == 2 && t > 0 && tid < 64) {
                int b = tid >> 3, ch = tid & 7;
                float p = 0.0f;
                #pragma unroll
                for (int m = 0; m < 16; ++m) {
                    int u = ch * 16 + m;
                    p += ubuf[q][b][128 + u] * swout[u];
                }
                p += __shfl_down_sync(0xffffffffu, p, 4, 8);
                p += __shfl_down_sync(0xffffffffu, p, 2, 8);
                p += __shfl_down_sync(0xffffffffu, p, 1, 8);
                if (ch == 0) out[(size_t)(t - 1) * BSZ + gb + b] = p + sbout;
            }

            {   // act
                float p0 = sg[ba][0][ua]        + sg[ba][1][ua]        + bi;
                float p1 = sg[ba][0][64+ua]     + sg[ba][1][64+ua]     + bf;
                float p2 = sg[ba][0][128+ua]    + sg[ba][1][128+ua]    + bg;
                float p3 = sg[ba][0][192+ua]    + sg[ba][1][192+ua]    + bo;
                float gi = sigf(p0), gf = sigf(p1);
                float gG = tanhfast(p2), go = sigf(p3);
                cst = gf * cst + gi * gG;
                float h = go * tanhfast(cst);
                ubuf[q ^ 1][ba][128 + ua] = h;                               // own
                st_dsmem(smem_u32(&ubuf[q ^ 1][ba][192 + ua]), peer, h);     // peer
            }
            __syncthreads();   // B3
            if (tid == 0) {
                fence_cluster();
                mbar_arrive_rk(mb + 16 + (unsigned)(q^1) * 8, peer);   // Q_full[q^1]
            }
        }

        // epilogue: out(TT-1), slot 0 (rank2)
        if (rank == 2 && tid < 64) {
            mbar_wait(mb + 16, (unsigned)pqf[0]);   // final Q_full[0]
            int b = tid >> 3, ch = tid & 7;
            float p = 0.0f;
            #pragma unroll
            for (int m = 0; m < 16; ++m) {
                int u = ch * 16 + m;
                p += ubuf[0][b][128 + u] * swout[u];
            }
            p += __shfl_down_sync(0xffffffffu, p, 4, 8);
            p += __shfl_down_sync(0xffffffffu, p, 2, 8);
            p += __shfl_down_sync(0xffffffffu, p, 1, 8);
            if (ch == 0) out[(size_t)(TT - 1) * BSZ + gb + b] = p + sbout;
        }
        CLUSTER_SYNC();
    }
}

extern "C" void kernel_launch(void* const* d_in, const int* in_sizes, int n_in,
                              void* d_out, int out_size)
{
    const float* state = (const float*)d_in[0];
    const float* W_ih0 = (const float*)d_in[1];
    const float* W_hh0 = (const float*)d_in[2];
    const float* b_ih0 = (const float*)d_in[3];
    const float* b_hh0 = (const float*)d_in[4];
    const float* W_ih1 = (const float*)d_in[5];
    const float* W_hh1 = (const float*)d_in[6];
    const float* b_ih1 = (const float*)d_in[7];
    const float* b_hh1 = (const float*)d_in[8];
    const float* W_out = (const float*)d_in[9];
    const float* b_out = (const float*)d_in[10];
    float* out = (float*)d_out;

    cudaFuncSetAttribute(lstm_kernel,
                         cudaFuncAttributeMaxDynamicSharedMemorySize, DYNSMEM);
    prep_kernel<<<224, 512>>>(W_ih0, W_hh0, W_ih1, W_hh1);
    lstm_kernel<<<NCTA, NTHR, DYNSMEM>>>(state, b_ih0, b_hh0, b_ih1, b_hh1,
                                         W_out, b_out, out);
}

// round 13
// speedup vs baseline: 1.1950x; 1.1950x over previous
#include <cuda_runtime.h>

#define TT    512
#define BSZ   256
#define DIN   64
#define HH    128
#define BPC   8
#define SPB   4          // batches per stream
#define NGRP  32
#define NTHR  512
#define RPC   256        // rows per CTA: 4 gates x 64 units
#define UPC   64
#define NB0   48         // k-blocks layer0 (K=192)
#define NB1   64         // k-blocks layer1 (K=256)
#define SKB1  48         // smem-resident kb (layer1)
#define NCTA  (NGRP*4)   // 128
#define DYNSMEM (48*RPC*16)   // 192 KB

// Blocked weights: [(half*NB + kb)*RPC + r] float4 = W[grow][4kb..4kb+3]
__device__ float4 g_W0B[2 * NB0 * RPC];
__device__ float4 g_W1B[2 * NB1 * RPC];

__global__ void prep_kernel(const float* __restrict__ Wih0,
                            const float* __restrict__ Whh0,
                            const float* __restrict__ Wih1,
                            const float* __restrict__ Whh1)
{
    int idx = blockIdx.x * blockDim.x + threadIdx.x;
    int stride = gridDim.x * blockDim.x;
    for (int e = idx; e < 2 * NB0 * RPC * 4; e += stride) {
        int i = e & 3, e2 = e >> 2;
        int r = e2 % RPC, e3 = e2 / RPC;
        int kb = e3 % NB0, half = e3 / NB0;
        int k = kb * 4 + i;
        int gate = r >> 6, ul = r & 63;
        int grow = gate * HH + half * UPC + ul;
        float v = (k < DIN) ? Wih0[grow * DIN + k] : Whh0[grow * HH + (k - DIN)];
        ((float*)g_W0B)[e] = v;
    }
    for (int e = idx; e < 2 * NB1 * RPC * 4; e += stride) {
        int i = e & 3, e2 = e >> 2;
        int r = e2 % RPC, e3 = e2 / RPC;
        int kb = e3 % NB1, half = e3 / NB1;
        int k = kb * 4 + i;
        int gate = r >> 6, ul = r & 63;
        int grow = gate * HH + half * UPC + ul;
        float v = (k < HH) ? Wih1[grow * HH + k] : Whh1[grow * HH + (k - HH)];
        ((float*)g_W1B)[e] = v;
    }
}

__device__ __forceinline__ void fma2(unsigned long long& d,
                                     unsigned long long a,
                                     unsigned long long b)
{
    asm("fma.rn.f32x2 %0, %1, %2, %0;" : "+l"(d) : "l"(a), "l"(b));
}
__device__ __forceinline__ float flo(unsigned long long v) {
    return __uint_as_float((unsigned)(v & 0xffffffffu));
}
__device__ __forceinline__ float fhi(unsigned long long v) {
    return __uint_as_float((unsigned)(v >> 32));
}
__device__ __forceinline__ float sigf(float x) {
    return __fdividef(1.0f, 1.0f + __expf(-x));
}
__device__ __forceinline__ float tanhfast(float x) {
    return 1.0f - __fdividef(2.0f, __expf(2.0f * x) + 1.0f);
}
__device__ __forceinline__ float ldcg(const float* p) {
    float v;
    asm volatile("ld.global.cg.f32 %0, [%1];" : "=f"(v) : "l"(p) : "memory");
    return v;
}
__device__ __forceinline__ ulonglong2 ldcg_u2(const ulonglong2* p) {
    ulonglong2 v;
    asm volatile("ld.global.cg.v2.u64 {%0,%1}, [%2];"
                 : "=l"(v.x), "=l"(v.y) : "l"(p) : "memory");
    return v;
}
__device__ __forceinline__ unsigned smem_u32(const void* p) {
    unsigned a;
    asm("{ .reg .u64 t; cvta.to.shared.u64 t, %1; cvt.u32.u64 %0, t; }"
        : "=r"(a) : "l"(p));
    return a;
}
__device__ __forceinline__ unsigned cta_rank() {
    unsigned r;
    asm("mov.u32 %0, %%cluster_ctarank;" : "=r"(r));
    return r;
}
__device__ __forceinline__ unsigned mapa_u32(unsigned a, unsigned rank) {
    unsigned r;
    asm("mapa.shared::cluster.u32 %0, %1, %2;" : "=r"(r) : "r"(a), "r"(rank));
    return r;
}
__device__ __forceinline__ void mbar_init(unsigned a, unsigned cnt) {
    asm volatile("mbarrier.init.shared.b64 [%0], %1;" :: "r"(a), "r"(cnt) : "memory");
}
__device__ __forceinline__ void mbar_arrive_rk(unsigned local_a, unsigned rank) {
    unsigned ra = mapa_u32(local_a, rank);
    asm volatile("mbarrier.arrive.release.cluster.shared::cluster.b64 _, [%0];"
                 :: "r"(ra) : "memory");
}
__device__ __forceinline__ void mbar_wait(unsigned a, unsigned parity) {
    asm volatile(
        "{\n\t.reg .pred P;\n\t"
        "W_%=:\n\t"
        "mbarrier.try_wait.parity.acquire.cluster.shared::cta.b64 P, [%0], %1, 0x989680;\n\t"
        "@P bra D_%=;\n\t"
        "bra W_%=;\n\t"
        "D_%=:\n\t}"
        :: "r"(a), "r"(parity) : "memory");
}
__device__ __forceinline__ void st_dsmem(unsigned local_a, unsigned rank, float v) {
    unsigned ra = mapa_u32(local_a, rank);
    asm volatile("st.shared::cluster.f32 [%0], %1;" :: "r"(ra), "f"(v) : "memory");
}
__device__ __forceinline__ void bar_s(int id) {
    asm volatile("bar.sync %0, %1;" :: "r"(id), "r"(256) : "memory");
}
#define CLUSTER_SYNC() do { \
    asm volatile("barrier.cluster.arrive.aligned;" ::: "memory"); \
    asm volatile("barrier.cluster.wait.aligned;" ::: "memory"); \
} while (0)

__global__ void __launch_bounds__(NTHR, 1) __cluster_dims__(4, 1, 1)
lstm_kernel(const float* __restrict__ state,
            const float* __restrict__ b_ih0, const float* __restrict__ b_hh0,
            const float* __restrict__ b_ih1, const float* __restrict__ b_hh1,
            const float* __restrict__ W_out, const float* __restrict__ b_out,
            float* __restrict__ out)
{
    extern __shared__ __align__(16) ulonglong2 ws[];   // resident weights (48 kb)

    // rows of 256 floats: L0 = [x 64 | h0 unit-order 128 | pad], L1 = [h0 | h1]
    __shared__ __align__(16) float ubuf[2][BPC][256];
    __shared__ float sg[2][SPB][2][RPC];   // [stream][batch][seg][row]
    __shared__ float swout[HH];
    __shared__ float sbout;
    __shared__ __align__(8) unsigned long long mbar[8];   // 4 per stream
    // L0: idx 0/1 = F[q] peer-h0 full (cnt1); idx 2/3 = E[q] L1-consumed (cnt2)
    // L1: idx 0/1 = H[q] h0 full (cnt2);     idx 2/3 = Q[q] peer-h1 full (cnt1)

    const int grp  = blockIdx.x >> 2;
    const int gb   = grp * BPC;
    const unsigned rank = cta_rank();
    const int tid  = threadIdx.x;
    const int s    = tid >> 8;            // stream 0/1
    const int lt   = tid & 255;           // local tid within stream
    const int seg  = lt >> 7;             // k-segment (dot phase)
    const int rt   = lt & 127;            // row pair base: rows rt, rt+128
    const int ba   = lt >> 6;             // act-phase local batch 0..3
    const int ua   = lt & 63;             // act-phase unit 0..63
    const int b    = s * SPB + ba;        // global batch in group
    const int barid = 1 + s;
    const unsigned mb = smem_u32(&mbar[0]);
#define MBAR(ss, ii) (mb + (unsigned)(((ss) * 4 + (ii)) * 8))

    if (tid == 0) {
        #pragma unroll
        for (int s2 = 0; s2 < 2; ++s2) {
            if (rank < 2) {
                mbar_init(MBAR(s2, 0), 1); mbar_init(MBAR(s2, 1), 1);
                mbar_init(MBAR(s2, 2), 2); mbar_init(MBAR(s2, 3), 2);
            } else {
                mbar_init(MBAR(s2, 0), 2); mbar_init(MBAR(s2, 1), 2);
                mbar_init(MBAR(s2, 2), 1); mbar_init(MBAR(s2, 3), 1);
            }
        }
    }

    if (rank < 2) {
        // ===================== L0 half-CTA =====================
        const int half = rank;
        const unsigned peer = rank ^ 1u;
        {   // all 48 kb of L0 weights -> smem (both streams cooperate)
            const ulonglong2* src = (const ulonglong2*)g_W0B + (size_t)half * NB0 * RPC;
            for (int e = tid; e < NB0 * RPC; e += NTHR) ws[e] = ldcg_u2(src + e);
        }
        const int gr0 = half * UPC + ua;
        const float bi = b_ih0[gr0]        + b_hh0[gr0];
        const float bf = b_ih0[HH+gr0]     + b_hh0[HH+gr0];
        const float bg = b_ih0[2*HH+gr0]   + b_hh0[2*HH+gr0];
        const float bo = b_ih0[3*HH+gr0]   + b_hh0[3*HH+gr0];
        ubuf[0][b][DIN + ua]      = 0.0f;   // h0(-1) = 0, both halves
        ubuf[0][b][DIN + 64 + ua] = 0.0f;
        ubuf[0][b][ua] = ldcg(state + (gb + b) * DIN + ua);   // x(0)
        float cst = 0.0f;
        int pf[2] = {0, 0}, pe[2] = {0, 0};
        __syncthreads();
        CLUSTER_SYNC();

        for (int t = 0; t < TT; ++t) {
            const int q = t & 1;
            float xr = 0.0f;
            if (t + 1 < TT)
                xr = ldcg(state + ((size_t)(t + 1) * BSZ + gb + b) * DIN + ua);
            if (lt == 0) {
                if (t == 0 && s == 1) __nanosleep(2000);   // phase stagger seed
                if (t > 0)  mbar_wait(MBAR(s, q),     (unsigned)pf[q]);
                if (t >= 2) mbar_wait(MBAR(s, 2 + q), (unsigned)pe[q]);
            }
            if (t > 0)  pf[q] ^= 1;
            if (t >= 2) pe[q] ^= 1;
            bar_s(barid);   // B1: slot q inputs complete
            ubuf[q ^ 1][b][ua] = xr;

            {   // dot: 2 rows (rt, rt+128) x 4 batches, kb = seg*24 .. +24
                unsigned long long acc[8];
                #pragma unroll
                for (int i = 0; i < 8; ++i) acc[i] = 0ull;
                const float* xb = &ubuf[q][s * SPB][0];
                const int kb0 = seg * 24;
                #pragma unroll 4
                for (int kb = 0; kb < 24; ++kb) {
                    const int kk = kb0 + kb;
                    ulonglong2 w0 = ws[(size_t)kk * RPC + rt];
                    ulonglong2 w1 = ws[(size_t)kk * RPC + rt + 128];
                    #pragma unroll
                    for (int bl = 0; bl < SPB; ++bl) {
                        ulonglong2 xv = ((const ulonglong2*)(xb + (size_t)bl * 256))[kk];
                        fma2(acc[bl],     w0.x, xv.x); fma2(acc[bl],     w0.y, xv.y);
                        fma2(acc[4 + bl], w1.x, xv.x); fma2(acc[4 + bl], w1.y, xv.y);
                    }
                }
                #pragma unroll
                for (int bl = 0; bl < SPB; ++bl) {
                    sg[s][bl][seg][rt]       = flo(acc[bl])     + fhi(acc[bl]);
                    sg[s][bl][seg][rt + 128] = flo(acc[4 + bl]) + fhi(acc[4 + bl]);
                }
            }
            bar_s(barid);   // B2

            {   // act
                float p0 = sg[s][ba][0][ua]      + sg[s][ba][1][ua]      + bi;
                float p1 = sg[s][ba][0][64+ua]   + sg[s][ba][1][64+ua]   + bf;
                float p2 = sg[s][ba][0][128+ua]  + sg[s][ba][1][128+ua]  + bg;
                float p3 = sg[s][ba][0][192+ua]  + sg[s][ba][1][192+ua]  + bo;
                float gi = sigf(p0), gf = sigf(p1);
                float gG = tanhfast(p2), go = sigf(p3);
                cst = gf * cst + gi * gG;
                float h = go * tanhfast(cst);
                float* lp = &ubuf[q ^ 1][b][DIN + gr0];
                *lp = h;                                     // own recurrence
                st_dsmem(smem_u32(lp), peer, h);             // peer L0, same offset
                unsigned l1a = smem_u32(&ubuf[q][b][gr0]);   // L1 h0 region (unit order)
                st_dsmem(l1a, 2u, h);
                st_dsmem(l1a, 3u, h);
            }
            bar_s(barid);   // B3
            if (lt == 0) {
                mbar_arrive_rk(MBAR(s, q ^ 1), peer);   // peer F[q^1]
                mbar_arrive_rk(MBAR(s, q), 2u);         // L1a H[q]
                mbar_arrive_rk(MBAR(s, q), 3u);         // L1b H[q]
            }
        }
        CLUSTER_SYNC();
    } else {
        // ===================== L1 half-CTA =====================
        const int half = rank - 2;
        const unsigned peer_rk = rank ^ 1u;
        {   // kb 0..47 of L1 weights -> smem; tail 48..63 stays in gmem (L1$)
            const ulonglong2* src = (const ulonglong2*)g_W1B + (size_t)half * NB1 * RPC;
            for (int e = tid; e < SKB1 * RPC; e += NTHR) ws[e] = ldcg_u2(src + e);
        }
        const ulonglong2* wg = (const ulonglong2*)g_W1B
                             + ((size_t)half * NB1 + 48) * RPC;   // kb 48..63
        const int gr0 = half * UPC + ua;
        const float bi = b_ih1[gr0]        + b_hh1[gr0];
        const float bf = b_ih1[HH+gr0]     + b_hh1[HH+gr0];
        const float bg = b_ih1[2*HH+gr0]   + b_hh1[2*HH+gr0];
        const float bo = b_ih1[3*HH+gr0]   + b_hh1[3*HH+gr0];
        if (rank == 2) {
            if (tid < HH) swout[tid] = W_out[tid];
            if (tid == 0) sbout = b_out[0];
        }
        ubuf[0][b][HH + ua]      = 0.0f;   // h1(-1) = 0, both halves
        ubuf[0][b][HH + 64 + ua] = 0.0f;
        float cst = 0.0f;
        int ph[2] = {0, 0}, pqf[2] = {0, 0};
        __syncthreads();
        CLUSTER_SYNC();

        for (int t = 0; t < TT; ++t) {
            const int q = t & 1;
            if (lt == 0) {
                if (t == 0 && s == 1) __nanosleep(2000);
                mbar_wait(MBAR(s, q), (unsigned)ph[q]);                   // h0(t)
                if (t > 0) mbar_wait(MBAR(s, 2 + q), (unsigned)pqf[q]);   // peer h1(t-1)
            }
            ph[q] ^= 1;
            if (t > 0) pqf[q] ^= 1;
            bar_s(barid);   // B1: slot q = [h0(t) | h1(t-1)] complete

            // head: out(t-1) for this stream's 4 batches (rank2 only)
            if (rank == 2 && t > 0 && lt < 32) {
                int bl = lt >> 3, ch = lt & 7;
                const float* hv = &ubuf[q][s * SPB + bl][HH];
                float p = 0.0f;
                #pragma unroll
                for (int m = 0; m < 16; ++m) {
                    int u = ch * 16 + m;
                    p += hv[u] * swout[u];
                }
                p += __shfl_down_sync(0xffffffffu, p, 4, 8);
                p += __shfl_down_sync(0xffffffffu, p, 2, 8);
                p += __shfl_down_sync(0xffffffffu, p, 1, 8);
                if (ch == 0)
                    out[(size_t)(t - 1) * BSZ + gb + s * SPB + bl] = p + sbout;
            }

            {   // dot: 2 rows x 4 batches over 32 kb (seg0: 0..31 smem;
                // seg1: 32..47 smem + 48..63 gmem)
                unsigned long long acc[8];
                #pragma unroll
                for (int i = 0; i < 8; ++i) acc[i] = 0ull;
                const float* xb = &ubuf[q][s * SPB][0];
                if (seg == 0) {
                    #pragma unroll 4
                    for (int kk = 0; kk < 32; ++kk) {
                        ulonglong2 w0 = ws[(size_t)kk * RPC + rt];
                        ulonglong2 w1 = ws[(size_t)kk * RPC + rt + 128];
                        #pragma unroll
                        for (int bl = 0; bl < SPB; ++bl) {
                            ulonglong2 xv = ((const ulonglong2*)(xb + (size_t)bl * 256))[kk];
                            fma2(acc[bl],     w0.x, xv.x); fma2(acc[bl],     w0.y, xv.y);
                            fma2(acc[4 + bl], w1.x, xv.x); fma2(acc[4 + bl], w1.y, xv.y);
                        }
                    }
                } else {
                    #pragma unroll 4
                    for (int kk = 32; kk < 48; ++kk) {
                        ulonglong2 w0 = ws[(size_t)kk * RPC + rt];
                        ulonglong2 w1 = ws[(size_t)kk * RPC + rt + 128];
                        #pragma unroll
                        for (int bl = 0; bl < SPB; ++bl) {
                            ulonglong2 xv = ((const ulonglong2*)(xb + (size_t)bl * 256))[kk];
                            fma2(acc[bl],     w0.x, xv.x); fma2(acc[bl],     w0.y, xv.y);
                            fma2(acc[4 + bl], w1.x, xv.x); fma2(acc[4 + bl], w1.y, xv.y);
                        }
                    }
                    #pragma unroll 4
                    for (int kt = 0; kt < 16; ++kt) {
                        const int kk = 48 + kt;
                        ulonglong2 w0 = wg[(size_t)kt * RPC + rt];         // L1$-cached
                        ulonglong2 w1 = wg[(size_t)kt * RPC + rt + 128];
                        #pragma unroll
                        for (int bl = 0; bl < SPB; ++bl) {
                            ulonglong2 xv = ((const ulonglong2*)(xb + (size_t)bl * 256))[kk];
                            fma2(acc[bl],     w0.x, xv.x); fma2(acc[bl],     w0.y, xv.y);
                            fma2(acc[4 + bl], w1.x, xv.x); fma2(acc[4 + bl], w1.y, xv.y);
                        }
                    }
                }
                #pragma unroll
                for (int bl = 0; bl < SPB; ++bl) {
                    sg[s][bl][seg][rt]       = flo(acc[bl])     + fhi(acc[bl]);
                    sg[s][bl][seg][rt + 128] = flo(acc[4 + bl]) + fhi(acc[4 + bl]);
                }
            }
            bar_s(barid);   // B2: slot-q reads done
            if (lt == 0) {   // release h0 slot q to both L0 CTAs
                mbar_arrive_rk(MBAR(s, 2 + q), 0u);
                mbar_arrive_rk(MBAR(s, 2 + q), 1u);
            }

            {   // act
                float p0 = sg[s][ba][0][ua]      + sg[s][ba][1][ua]      + bi;
                float p1 = sg[s][ba][0][64+ua]   + sg[s][ba][1][64+ua]   + bf;
                float p2 = sg[s][ba][0][128+ua]  + sg[s][ba][1][128+ua]  + bg;
                float p3 = sg[s][ba][0][192+ua]  + sg[s][ba][1][192+ua]  + bo;
                float gi = sigf(p0), gf = sigf(p1);
                float gG = tanhfast(p2), go = sigf(p3);
                cst = gf * cst + gi * gG;
                float h = go * tanhfast(cst);
                float* lp = &ubuf[q ^ 1][b][HH + gr0];
                *lp = h;                                  // own recurrence
                st_dsmem(smem_u32(lp), peer_rk, h);       // peer L1, same offset
            }
            bar_s(barid);   // B3
            if (lt == 0)
                mbar_arrive_rk(MBAR(s, 2 + (q ^ 1)), peer_rk);   // peer Q[q^1]
        }

        // epilogue: out(TT-1) per stream (rank2)
        if (rank == 2 && lt < 32) {
            mbar_wait(MBAR(s, 2 + 0), (unsigned)pqf[0]);   // peer h1(TT-1) in slot 0
            int bl = lt >> 3, ch = lt & 7;
            const float* hv = &ubuf[0][s * SPB + bl][HH];
            float p = 0.0f;
            #pragma unroll
            for (int m = 0; m < 16; ++m) {
                int u = ch * 16 + m;
                p += hv[u] * swout[u];
            }
            p += __shfl_down_sync(0xffffffffu, p, 4, 8);
            p += __shfl_down_sync(0xffffffffu, p, 2, 8);
            p += __shfl_down_sync(0xffffffffu, p, 1, 8);
            if (ch == 0)
                out[(size_t)(TT - 1) * BSZ + gb + s * SPB + bl] = p + sbout;
        }
        CLUSTER_SYNC();
    }
#undef MBAR
}

extern "C" void kernel_launch(void* const* d_in, const int* in_sizes, int n_in,
                              void* d_out, int out_size)
{
    const float* state = (const float*)d_in[0];
    const float* W_ih0 = (const float*)d_in[1];
    const float* W_hh0 = (const float*)d_in[2];
    const float* b_ih0 = (const float*)d_in[3];
    const float* b_hh0 = (const float*)d_in[4];
    const float* W_ih1 = (const float*)d_in[5];
    const float* W_hh1 = (const float*)d_in[6];
    const float* b_ih1 = (const float*)d_in[7];
    const float* b_hh1 = (const float*)d_in[8];
    const float* W_out = (const float*)d_in[9];
    const float* b_out = (const float*)d_in[10];
    float* out = (float*)d_out;

    cudaFuncSetAttribute(lstm_kernel,
                         cudaFuncAttributeMaxDynamicSharedMemorySize, DYNSMEM);
    prep_kernel<<<224, 512>>>(W_ih0, W_hh0, W_ih1, W_hh1);
    lstm_kernel<<<NCTA, NTHR, DYNSMEM>>>(state, b_ih0, b_hh0, b_ih1, b_hh1,
                                         W_out, b_out, out);
}

// round 14
// speedup vs baseline: 1.4496x; 1.2131x over previous
#include <cuda_runtime.h>

#define TT    512
#define BSZ   256
#define DIN   64
#define HH    128
#define BPC   8
#define SPB   4          // batches per stream
#define NGRP  32
#define NTHR  512
#define RPC   256        // rows per CTA: 4 gates x 64 units
#define UPC   64
#define NB0   48         // k-blocks layer0 (K=192)
#define NB1   64         // k-blocks layer1 (K=256)
#define SKB1  48         // smem-resident kb (layer1)
#define NCTA  (NGRP*4)   // 128
#define DYNSMEM (48*RPC*16)   // 192 KB

// Blocked weights: [(half*NB + kb)*RPC + r] float4 = W[grow][4kb..4kb+3]
__device__ float4 g_W0B[2 * NB0 * RPC];
__device__ float4 g_W1B[2 * NB1 * RPC];

__global__ void prep_kernel(const float* __restrict__ Wih0,
                            const float* __restrict__ Whh0,
                            const float* __restrict__ Wih1,
                            const float* __restrict__ Whh1)
{
    int idx = blockIdx.x * blockDim.x + threadIdx.x;
    int stride = gridDim.x * blockDim.x;
    for (int e = idx; e < 2 * NB0 * RPC * 4; e += stride) {
        int i = e & 3, e2 = e >> 2;
        int r = e2 % RPC, e3 = e2 / RPC;
        int kb = e3 % NB0, half = e3 / NB0;
        int k = kb * 4 + i;
        int gate = r >> 6, ul = r & 63;
        int grow = gate * HH + half * UPC + ul;
        float v = (k < DIN) ? Wih0[grow * DIN + k] : Whh0[grow * HH + (k - DIN)];
        ((float*)g_W0B)[e] = v;
    }
    for (int e = idx; e < 2 * NB1 * RPC * 4; e += stride) {
        int i = e & 3, e2 = e >> 2;
        int r = e2 % RPC, e3 = e2 / RPC;
        int kb = e3 % NB1, half = e3 / NB1;
        int k = kb * 4 + i;
        int gate = r >> 6, ul = r & 63;
        int grow = gate * HH + half * UPC + ul;
        float v = (k < HH) ? Wih1[grow * HH + k] : Whh1[grow * HH + (k - HH)];
        ((float*)g_W1B)[e] = v;
    }
}

__device__ __forceinline__ void fma2(unsigned long long& d,
                                     unsigned long long a,
                                     unsigned long long b)
{
    asm("fma.rn.f32x2 %0, %1, %2, %0;" : "+l"(d) : "l"(a), "l"(b));
}
__device__ __forceinline__ float flo(unsigned long long v) {
    return __uint_as_float((unsigned)(v & 0xffffffffu));
}
__device__ __forceinline__ float fhi(unsigned long long v) {
    return __uint_as_float((unsigned)(v >> 32));
}
__device__ __forceinline__ float sigf(float x) {
    return __fdividef(1.0f, 1.0f + __expf(-x));
}
__device__ __forceinline__ float tanhfast(float x) {
    return 1.0f - __fdividef(2.0f, __expf(2.0f * x) + 1.0f);
}
__device__ __forceinline__ float ldcg(const float* p) {
    float v;
    asm volatile("ld.global.cg.f32 %0, [%1];" : "=f"(v) : "l"(p) : "memory");
    return v;
}
__device__ __forceinline__ ulonglong2 ldcg_u2(const ulonglong2* p) {
    ulonglong2 v;
    asm volatile("ld.global.cg.v2.u64 {%0,%1}, [%2];"
                 : "=l"(v.x), "=l"(v.y) : "l"(p) : "memory");
    return v;
}
__device__ __forceinline__ unsigned smem_u32(const void* p) {
    unsigned a;
    asm("{ .reg .u64 t; cvta.to.shared.u64 t, %1; cvt.u32.u64 %0, t; }"
        : "=r"(a) : "l"(p));
    return a;
}
__device__ __forceinline__ unsigned cta_rank() {
    unsigned r;
    asm("mov.u32 %0, %%cluster_ctarank;" : "=r"(r));
    return r;
}
__device__ __forceinline__ unsigned mapa_u32(unsigned a, unsigned rank) {
    unsigned r;
    asm("mapa.shared::cluster.u32 %0, %1, %2;" : "=r"(r) : "r"(a), "r"(rank));
    return r;
}
__device__ __forceinline__ void mbar_init(unsigned a, unsigned cnt) {
    asm volatile("mbarrier.init.shared.b64 [%0], %1;" :: "r"(a), "r"(cnt) : "memory");
}
__device__ __forceinline__ void mbar_arrive_rk(unsigned local_a, unsigned rank) {
    unsigned ra = mapa_u32(local_a, rank);
    asm volatile("mbarrier.arrive.release.cluster.shared::cluster.b64 _, [%0];"
                 :: "r"(ra) : "memory");
}
__device__ __forceinline__ void mbar_wait(unsigned a, unsigned parity) {
    asm volatile(
        "{\n\t.reg .pred P;\n\t"
        "W_%=:\n\t"
        "mbarrier.try_wait.parity.acquire.cluster.shared::cta.b64 P, [%0], %1, 0x989680;\n\t"
        "@P bra D_%=;\n\t"
        "bra W_%=;\n\t"
        "D_%=:\n\t}"
        :: "r"(a), "r"(parity) : "memory");
}
__device__ __forceinline__ void st_dsmem(unsigned local_a, unsigned rank, float v) {
    unsigned ra = mapa_u32(local_a, rank);
    asm volatile("st.shared::cluster.f32 [%0], %1;" :: "r"(ra), "f"(v) : "memory");
}
__device__ __forceinline__ void bar_s(int id) {
    asm volatile("bar.sync %0, %1;" :: "r"(id), "r"(256) : "memory");
}
// cross-stream dot token: producers arrive, consumer syncs (count 512)
__device__ __forceinline__ void tok_arrive(int id) {
    asm volatile("bar.arrive %0, %1;" :: "r"(id), "r"(512) : "memory");
}
__device__ __forceinline__ void tok_wait(int id) {
    asm volatile("bar.sync %0, %1;" :: "r"(id), "r"(512) : "memory");
}
#define CLUSTER_SYNC() do { \
    asm volatile("barrier.cluster.arrive.aligned;" ::: "memory"); \
    asm volatile("barrier.cluster.wait.aligned;" ::: "memory"); \
} while (0)

__global__ void __launch_bounds__(NTHR, 1) __cluster_dims__(4, 1, 1)
lstm_kernel(const float* __restrict__ state,
            const float* __restrict__ b_ih0, const float* __restrict__ b_hh0,
            const float* __restrict__ b_ih1, const float* __restrict__ b_hh1,
            const float* __restrict__ W_out, const float* __restrict__ b_out,
            float* __restrict__ out)
{
    extern __shared__ __align__(16) ulonglong2 ws[];   // resident weights (48 kb)

    // rows of 256 floats: L0 = [x 64 | h0 128 | pad], L1 = [h0 | h1]
    __shared__ __align__(16) float ubuf[2][BPC][256];
    __shared__ float sg[2][SPB][2][RPC];   // [stream][batch][seg][row]
    __shared__ float swout[HH];
    __shared__ float sbout;
    __shared__ __align__(8) unsigned long long mbar[8];   // 4 per stream
    // L0: idx 0/1 = F[q] peer-h0 full (cnt1); idx 2/3 = E[q] L1-consumed (cnt2)
    // L1: idx 0/1 = H[q] h0 full (cnt2);     idx 2/3 = Q[q] peer-h1 full (cnt1)

    const int grp  = blockIdx.x >> 2;
    const int gb   = grp * BPC;
    const unsigned rank = cta_rank();
    const int tid  = threadIdx.x;
    const int s    = tid >> 8;            // stream 0/1
    const int lt   = tid & 255;           // local tid within stream
    const int seg  = lt >> 7;             // k-segment (dot phase)
    const int rt   = lt & 127;            // row pair base: rows rt, rt+128
    const int ba   = lt >> 6;             // act-phase local batch 0..3
    const int ua   = lt & 63;             // act-phase unit 0..63
    const int b    = s * SPB + ba;        // global batch in group
    const int barid = 1 + s;
    const unsigned mb = smem_u32(&mbar[0]);
#define MBAR(ss, ii) (mb + (unsigned)(((ss) * 4 + (ii)) * 8))

    if (tid == 0) {
        #pragma unroll
        for (int s2 = 0; s2 < 2; ++s2) {
            if (rank < 2) {
                mbar_init(MBAR(s2, 0), 1); mbar_init(MBAR(s2, 1), 1);
                mbar_init(MBAR(s2, 2), 2); mbar_init(MBAR(s2, 3), 2);
            } else {
                mbar_init(MBAR(s2, 0), 2); mbar_init(MBAR(s2, 1), 2);
                mbar_init(MBAR(s2, 2), 1); mbar_init(MBAR(s2, 3), 1);
            }
        }
    }

    if (rank < 2) {
        // ===================== L0 half-CTA =====================
        const int half = rank;
        const unsigned peer = rank ^ 1u;
        {   // all 48 kb of L0 weights -> smem (both streams cooperate)
            const ulonglong2* src = (const ulonglong2*)g_W0B + (size_t)half * NB0 * RPC;
            for (int e = tid; e < NB0 * RPC; e += NTHR) ws[e] = ldcg_u2(src + e);
        }
        const int gr0 = half * UPC + ua;
        const float bi = b_ih0[gr0]        + b_hh0[gr0];
        const float bf = b_ih0[HH+gr0]     + b_hh0[HH+gr0];
        const float bg = b_ih0[2*HH+gr0]   + b_hh0[2*HH+gr0];
        const float bo = b_ih0[3*HH+gr0]   + b_hh0[3*HH+gr0];
        ubuf[0][b][DIN + ua]      = 0.0f;   // h0(-1) = 0, both halves
        ubuf[0][b][DIN + 64 + ua] = 0.0f;
        ubuf[0][b][ua] = ldcg(state + (gb + b) * DIN + ua);   // x(0)
        float cst = 0.0f;
        int pf[2] = {0, 0}, pe[2] = {0, 0};
        __syncthreads();
        CLUSTER_SYNC();

        for (int t = 0; t < TT; ++t) {
            const int q = t & 1;
            float xr = 0.0f;
            if (t + 1 < TT)
                xr = ldcg(state + ((size_t)(t + 1) * BSZ + gb + b) * DIN + ua);
            if (lt == 0) {
                if (t > 0)  mbar_wait(MBAR(s, q),     (unsigned)pf[q]);
                if (t >= 2) mbar_wait(MBAR(s, 2 + q), (unsigned)pe[q]);
            }
            if (t > 0)  pf[q] ^= 1;
            if (t >= 2) pe[q] ^= 1;
            bar_s(barid);   // B1: slot q inputs complete
            ubuf[q ^ 1][b][ua] = xr;

            // ---- dot token: enforce s0(t) -> s1(t) -> s0(t+1) ordering ----
            if (s == 0) { if (t > 0) tok_wait(4); }
            else       { tok_wait(3); }

            {   // dot: 2 rows (rt, rt+128) x 4 batches, kb = seg*24 .. +24
                unsigned long long acc[8];
                #pragma unroll
                for (int i = 0; i < 8; ++i) acc[i] = 0ull;
                const float* xb = &ubuf[q][s * SPB][0];
                const int kb0 = seg * 24;
                #pragma unroll 4
                for (int kb = 0; kb < 24; ++kb) {
                    const int kk = kb0 + kb;
                    ulonglong2 w0 = ws[(size_t)kk * RPC + rt];
                    ulonglong2 w1 = ws[(size_t)kk * RPC + rt + 128];
                    #pragma unroll
                    for (int bl = 0; bl < SPB; ++bl) {
                        ulonglong2 xv = ((const ulonglong2*)(xb + (size_t)bl * 256))[kk];
                        fma2(acc[bl],     w0.x, xv.x); fma2(acc[bl],     w0.y, xv.y);
                        fma2(acc[4 + bl], w1.x, xv.x); fma2(acc[4 + bl], w1.y, xv.y);
                    }
                }
                #pragma unroll
                for (int bl = 0; bl < SPB; ++bl) {
                    sg[s][bl][seg][rt]       = flo(acc[bl])     + fhi(acc[bl]);
                    sg[s][bl][seg][rt + 128] = flo(acc[4 + bl]) + fhi(acc[4 + bl]);
                }
            }
            // release port token to the other stream
            if (s == 0) tok_arrive(3); else tok_arrive(4);
            bar_s(barid);   // B2

            {   // act
                float p0 = sg[s][ba][0][ua]      + sg[s][ba][1][ua]      + bi;
                float p1 = sg[s][ba][0][64+ua]   + sg[s][ba][1][64+ua]   + bf;
                float p2 = sg[s][ba][0][128+ua]  + sg[s][ba][1][128+ua]  + bg;
                float p3 = sg[s][ba][0][192+ua]  + sg[s][ba][1][192+ua]  + bo;
                float gi = sigf(p0), gf = sigf(p1);
                float gG = tanhfast(p2), go = sigf(p3);
                cst = gf * cst + gi * gG;
                float h = go * tanhfast(cst);
                float* lp = &ubuf[q ^ 1][b][DIN + gr0];
                *lp = h;                                     // own recurrence
                st_dsmem(smem_u32(lp), peer, h);             // peer L0, same offset
                unsigned l1a = smem_u32(&ubuf[q][b][gr0]);   // L1 h0 region
                st_dsmem(l1a, 2u, h);
                st_dsmem(l1a, 3u, h);
            }
            bar_s(barid);   // B3
            if (lt == 0) {
                mbar_arrive_rk(MBAR(s, q ^ 1), peer);   // peer F[q^1]
                mbar_arrive_rk(MBAR(s, q), 2u);         // L1a H[q]
                mbar_arrive_rk(MBAR(s, q), 3u);         // L1b H[q]
            }
        }
        CLUSTER_SYNC();
    } else {
        // ===================== L1 half-CTA =====================
        const int half = rank - 2;
        const unsigned peer_rk = rank ^ 1u;
        {   // kb 0..47 of L1 weights -> smem; tail 48..63 stays in gmem (L2)
            const ulonglong2* src = (const ulonglong2*)g_W1B + (size_t)half * NB1 * RPC;
            for (int e = tid; e < SKB1 * RPC; e += NTHR) ws[e] = ldcg_u2(src + e);
        }
        const ulonglong2* wg = (const ulonglong2*)g_W1B
                             + ((size_t)half * NB1 + 48) * RPC;   // kb 48..63
        const int gr0 = half * UPC + ua;
        const float bi = b_ih1[gr0]        + b_hh1[gr0];
        const float bf = b_ih1[HH+gr0]     + b_hh1[HH+gr0];
        const float bg = b_ih1[2*HH+gr0]   + b_hh1[2*HH+gr0];
        const float bo = b_ih1[3*HH+gr0]   + b_hh1[3*HH+gr0];
        if (rank == 2) {
            if (tid < HH) swout[tid] = W_out[tid];
            if (tid == 0) sbout = b_out[0];
        }
        ubuf[0][b][HH + ua]      = 0.0f;   // h1(-1) = 0, both halves
        ubuf[0][b][HH + 64 + ua] = 0.0f;
        float cst = 0.0f;
        int ph[2] = {0, 0}, pqf[2] = {0, 0};
        __syncthreads();
        CLUSTER_SYNC();

        for (int t = 0; t < TT; ++t) {
            const int q = t & 1;
            if (lt == 0) {
                mbar_wait(MBAR(s, q), (unsigned)ph[q]);                   // h0(t)
                if (t > 0) mbar_wait(MBAR(s, 2 + q), (unsigned)pqf[q]);   // peer h1(t-1)
            }
            ph[q] ^= 1;
            if (t > 0) pqf[q] ^= 1;
            bar_s(barid);   // B1: slot q = [h0(t) | h1(t-1)] complete

            // head: out(t-1) for this stream's 4 batches (rank2 only)
            if (rank == 2 && t > 0 && lt < 32) {
                int bl = lt >> 3, ch = lt & 7;
                const float* hv = &ubuf[q][s * SPB + bl][HH];
                float p = 0.0f;
                #pragma unroll
                for (int m = 0; m < 16; ++m) {
                    int u = ch * 16 + m;
                    p += hv[u] * swout[u];
                }
                p += __shfl_down_sync(0xffffffffu, p, 4, 8);
                p += __shfl_down_sync(0xffffffffu, p, 2, 8);
                p += __shfl_down_sync(0xffffffffu, p, 1, 8);
                if (ch == 0)
                    out[(size_t)(t - 1) * BSZ + gb + s * SPB + bl] = p + sbout;
            }

            // ---- dot token ----
            if (s == 0) { if (t > 0) tok_wait(4); }
            else       { tok_wait(3); }

            {   // dot: 2 rows x 4 batches over 32 kb
                // seg0: kb 0..31 smem; seg1: gmem tail FIRST (MLP), then smem
                unsigned long long acc[8];
                #pragma unroll
                for (int i = 0; i < 8; ++i) acc[i] = 0ull;
                const float* xb = &ubuf[q][s * SPB][0];
                if (seg == 0) {
                    #pragma unroll 4
                    for (int kk = 0; kk < 32; ++kk) {
                        ulonglong2 w0 = ws[(size_t)kk * RPC + rt];
                        ulonglong2 w1 = ws[(size_t)kk * RPC + rt + 128];
                        #pragma unroll
                        for (int bl = 0; bl < SPB; ++bl) {
                            ulonglong2 xv = ((const ulonglong2*)(xb + (size_t)bl * 256))[kk];
                            fma2(acc[bl],     w0.x, xv.x); fma2(acc[bl],     w0.y, xv.y);
                            fma2(acc[4 + bl], w1.x, xv.x); fma2(acc[4 + bl], w1.y, xv.y);
                        }
                    }
                } else {
                    #pragma unroll 4
                    for (int kt = 0; kt < 16; ++kt) {   // L2 tail first: deep MLP
                        const int kk = 48 + kt;
                        ulonglong2 w0 = ldcg_u2(wg + (size_t)kt * RPC + rt);
                        ulonglong2 w1 = ldcg_u2(wg + (size_t)kt * RPC + rt + 128);
                        #pragma unroll
                        for (int bl = 0; bl < SPB; ++bl) {
                            ulonglong2 xv = ((const ulonglong2*)(xb + (size_t)bl * 256))[kk];
                            fma2(acc[bl],     w0.x, xv.x); fma2(acc[bl],     w0.y, xv.y);
                            fma2(acc[4 + bl], w1.x, xv.x); fma2(acc[4 + bl], w1.y, xv.y);
                        }
                    }
                    #pragma unroll 4
                    for (int kk = 32; kk < 48; ++kk) {
                        ulonglong2 w0 = ws[(size_t)kk * RPC + rt];
                        ulonglong2 w1 = ws[(size_t)kk * RPC + rt + 128];
                        #pragma unroll
                        for (int bl = 0; bl < SPB; ++bl) {
                            ulonglong2 xv = ((const ulonglong2*)(xb + (size_t)bl * 256))[kk];
                            fma2(acc[bl],     w0.x, xv.x); fma2(acc[bl],     w0.y, xv.y);
                            fma2(acc[4 + bl], w1.x, xv.x); fma2(acc[4 + bl], w1.y, xv.y);
                        }
                    }
                }
                #pragma unroll
                for (int bl = 0; bl < SPB; ++bl) {
                    sg[s][bl][seg][rt]       = flo(acc[bl])     + fhi(acc[bl]);
                    sg[s][bl][seg][rt + 128] = flo(acc[4 + bl]) + fhi(acc[4 + bl]);
                }
            }
            if (s == 0) tok_arrive(3); else tok_arrive(4);
            bar_s(barid);   // B2: slot-q reads done
            if (lt == 0) {   // release h0 slot q to both L0 CTAs
                mbar_arrive_rk(MBAR(s, 2 + q), 0u);
                mbar_arrive_rk(MBAR(s, 2 + q), 1u);
            }

            {   // act
                float p0 = sg[s][ba][0][ua]      + sg[s][ba][1][ua]      + bi;
                float p1 = sg[s][ba][0][64+ua]   + sg[s][ba][1][64+ua]   + bf;
                float p2 = sg[s][ba][0][128+ua]  + sg[s][ba][1][128+ua]  + bg;
                float p3 = sg[s][ba][0][192+ua]  + sg[s][ba][1][192+ua]  + bo;
                float gi = sigf(p0), gf = sigf(p1);
                float gG = tanhfast(p2), go = sigf(p3);
                cst = gf * cst + gi * gG;
                float h = go * tanhfast(cst);
                float* lp = &ubuf[q ^ 1][b][HH + gr0];
                *lp = h;                                  // own recurrence
                st_dsmem(smem_u32(lp), peer_rk, h);       // peer L1, same offset
            }
            bar_s(barid);   // B3
            if (lt == 0)
                mbar_arrive_rk(MBAR(s, 2 + (q ^ 1)), peer_rk);   // peer Q[q^1]
        }

        // epilogue: out(TT-1) per stream (rank2)
        if (rank == 2 && lt < 32) {
            mbar_wait(MBAR(s, 2 + 0), (unsigned)pqf[0]);   // peer h1(TT-1), slot 0
            int bl = lt >> 3, ch = lt & 7;
            const float* hv = &ubuf[0][s * SPB + bl][HH];
            float p = 0.0f;
            #pragma unroll
            for (int m = 0; m < 16; ++m) {
                int u = ch * 16 + m;
                p += hv[u] * swout[u];
            }
            p += __shfl_down_sync(0xffffffffu, p, 4, 8);
            p += __shfl_down_sync(0xffffffffu, p, 2, 8);
            p += __shfl_down_sync(0xffffffffu, p, 1, 8);
            if (ch == 0)
                out[(size_t)(TT - 1) * BSZ + gb + s * SPB + bl] = p + sbout;
        }
        CLUSTER_SYNC();
    }
#undef MBAR
}

extern "C" void kernel_launch(void* const* d_in, const int* in_sizes, int n_in,
                              void* d_out, int out_size)
{
    const float* state = (const float*)d_in[0];
    const float* W_ih0 = (const float*)d_in[1];
    const float* W_hh0 = (const float*)d_in[2];
    const float* b_ih0 = (const float*)d_in[3];
    const float* b_hh0 = (const float*)d_in[4];
    const float* W_ih1 = (const float*)d_in[5];
    const float* W_hh1 = (const float*)d_in[6];
    const float* b_ih1 = (const float*)d_in[7];
    const float* b_hh1 = (const float*)d_in[8];
    const float* W_out = (const float*)d_in[9];
    const float* b_out = (const float*)d_in[10];
    float* out = (float*)d_out;

    cudaFuncSetAttribute(lstm_kernel,
                         cudaFuncAttributeMaxDynamicSharedMemorySize, DYNSMEM);
    prep_kernel<<<224, 512>>>(W_ih0, W_hh0, W_ih1, W_hh1);
    lstm_kernel<<<NCTA, NTHR, DYNSMEM>>>(state, b_ih0, b_hh0, b_ih1, b_hh1,
                                         W_out, b_out, out);
}

// round 15
// speedup vs baseline: 1.4519x; 1.0016x over previous
#include <cuda_runtime.h>

#define TT    512
#define BSZ   256
#define DIN   64
#define HH    128
#define BPC   8
#define SPB   4          // batches per stream
#define NGRP  32
#define NTHR  512
#define RPC   256        // rows per CTA: 4 gates x 64 units
#define UPC   64
#define NB0   48         // k-blocks layer0 (K=192)
#define NB1   64         // k-blocks layer1 (K=256)
#define SKB1  48         // smem-resident kb (layer1)
#define NCTA  (NGRP*4)   // 128
#define DYNSMEM (48*RPC*16)   // 192 KB

// Blocked weights: [(half*NB + kb)*RPC + r] float4 = W[grow][4kb..4kb+3]
__device__ float4 g_W0B[2 * NB0 * RPC];
__device__ float4 g_W1B[2 * NB1 * RPC];

__global__ void prep_kernel(const float* __restrict__ Wih0,
                            const float* __restrict__ Whh0,
                            const float* __restrict__ Wih1,
                            const float* __restrict__ Whh1)
{
    int idx = blockIdx.x * blockDim.x + threadIdx.x;
    int stride = gridDim.x * blockDim.x;
    for (int e = idx; e < 2 * NB0 * RPC * 4; e += stride) {
        int i = e & 3, e2 = e >> 2;
        int r = e2 % RPC, e3 = e2 / RPC;
        int kb = e3 % NB0, half = e3 / NB0;
        int k = kb * 4 + i;
        int gate = r >> 6, ul = r & 63;
        int grow = gate * HH + half * UPC + ul;
        float v = (k < DIN) ? Wih0[grow * DIN + k] : Whh0[grow * HH + (k - DIN)];
        ((float*)g_W0B)[e] = v;
    }
    for (int e = idx; e < 2 * NB1 * RPC * 4; e += stride) {
        int i = e & 3, e2 = e >> 2;
        int r = e2 % RPC, e3 = e2 / RPC;
        int kb = e3 % NB1, half = e3 / NB1;
        int k = kb * 4 + i;
        int gate = r >> 6, ul = r & 63;
        int grow = gate * HH + half * UPC + ul;
        float v = (k < HH) ? Wih1[grow * HH + k] : Whh1[grow * HH + (k - HH)];
        ((float*)g_W1B)[e] = v;
    }
}

__device__ __forceinline__ void fma2(unsigned long long& d,
                                     unsigned long long a,
                                     unsigned long long b)
{
    asm("fma.rn.f32x2 %0, %1, %2, %0;" : "+l"(d) : "l"(a), "l"(b));
}
__device__ __forceinline__ float flo(unsigned long long v) {
    return __uint_as_float((unsigned)(v & 0xffffffffu));
}
__device__ __forceinline__ float fhi(unsigned long long v) {
    return __uint_as_float((unsigned)(v >> 32));
}
__device__ __forceinline__ float sigf(float x) {
    return __fdividef(1.0f, 1.0f + __expf(-x));
}
__device__ __forceinline__ float tanhfast(float x) {
    return 1.0f - __fdividef(2.0f, __expf(2.0f * x) + 1.0f);
}
__device__ __forceinline__ float ldcg(const float* p) {
    float v;
    asm volatile("ld.global.cg.f32 %0, [%1];" : "=f"(v) : "l"(p) : "memory");
    return v;
}
__device__ __forceinline__ ulonglong2 ldcg_u2(const ulonglong2* p) {
    ulonglong2 v;
    asm volatile("ld.global.cg.v2.u64 {%0,%1}, [%2];"
                 : "=l"(v.x), "=l"(v.y) : "l"(p) : "memory");
    return v;
}
__device__ __forceinline__ unsigned smem_u32(const void* p) {
    unsigned a;
    asm("{ .reg .u64 t; cvta.to.shared.u64 t, %1; cvt.u32.u64 %0, t; }"
        : "=r"(a) : "l"(p));
    return a;
}
__device__ __forceinline__ unsigned cta_rank() {
    unsigned r;
    asm("mov.u32 %0, %%cluster_ctarank;" : "=r"(r));
    return r;
}
__device__ __forceinline__ unsigned mapa_u32(unsigned a, unsigned rank) {
    unsigned r;
    asm("mapa.shared::cluster.u32 %0, %1, %2;" : "=r"(r) : "r"(a), "r"(rank));
    return r;
}
__device__ __forceinline__ void mbar_init(unsigned a, unsigned cnt) {
    asm volatile("mbarrier.init.shared.b64 [%0], %1;" :: "r"(a), "r"(cnt) : "memory");
}
__device__ __forceinline__ void mbar_arrive_rk(unsigned local_a, unsigned rank) {
    unsigned ra = mapa_u32(local_a, rank);
    asm volatile("mbarrier.arrive.release.cluster.shared::cluster.b64 _, [%0];"
                 :: "r"(ra) : "memory");
}
__device__ __forceinline__ void mbar_wait(unsigned a, unsigned parity) {
    asm volatile(
        "{\n\t.reg .pred P;\n\t"
        "W_%=:\n\t"
        "mbarrier.try_wait.parity.acquire.cluster.shared::cta.b64 P, [%0], %1, 0x989680;\n\t"
        "@P bra D_%=;\n\t"
        "bra W_%=;\n\t"
        "D_%=:\n\t}"
        :: "r"(a), "r"(parity) : "memory");
}
__device__ __forceinline__ void st_dsmem(unsigned local_a, unsigned rank, float v) {
    unsigned ra = mapa_u32(local_a, rank);
    asm volatile("st.shared::cluster.f32 [%0], %1;" :: "r"(ra), "f"(v) : "memory");
}
__device__ __forceinline__ void bar_s(int id) {
    asm volatile("bar.sync %0, %1;" :: "r"(id), "r"(256) : "memory");
}
// cross-stream dot token: producers arrive, consumer syncs (count 512)
__device__ __forceinline__ void tok_arrive(int id) {
    asm volatile("bar.arrive %0, %1;" :: "r"(id), "r"(512) : "memory");
}
__device__ __forceinline__ void tok_wait(int id) {
    asm volatile("bar.sync %0, %1;" :: "r"(id), "r"(512) : "memory");
}
#define CLUSTER_SYNC() do { \
    asm volatile("barrier.cluster.arrive.aligned;" ::: "memory"); \
    asm volatile("barrier.cluster.wait.aligned;" ::: "memory"); \
} while (0)

__global__ void __launch_bounds__(NTHR, 1) __cluster_dims__(4, 1, 1)
lstm_kernel(const float* __restrict__ state,
            const float* __restrict__ b_ih0, const float* __restrict__ b_hh0,
            const float* __restrict__ b_ih1, const float* __restrict__ b_hh1,
            const float* __restrict__ W_out, const float* __restrict__ b_out,
            float* __restrict__ out)
{
    extern __shared__ __align__(16) ulonglong2 ws[];   // resident weights (48 kb)

    // rows of 256 floats: L0 = [x 64 | h0 128 | pad], L1 = [h0 | h1]
    __shared__ __align__(16) float ubuf[2][BPC][256];
    __shared__ float sg[2][SPB][2][RPC];   // [stream][batch][seg][row]
    __shared__ float swout[HH];
    __shared__ float sbout;
    __shared__ __align__(8) unsigned long long mbar[8];   // 4 per stream
    // L0: idx 0/1 = F[q] peer-h0 full (cnt1); idx 2/3 = E[q] L1-consumed (cnt2)
    // L1: idx 0/1 = H[q] h0 full (cnt2);     idx 2/3 = Q[q] peer-h1 full (cnt1)

    const int grp  = blockIdx.x >> 2;
    const int gb   = grp * BPC;
    const unsigned rank = cta_rank();
    const int tid  = threadIdx.x;
    const int s    = tid >> 8;            // stream 0/1
    const int lt   = tid & 255;           // local tid within stream
    const int seg  = lt >> 7;             // k-segment (dot phase)
    const int rt   = lt & 127;            // row pair base: rows rt, rt+128
    const int ba   = lt >> 6;             // act-phase local batch 0..3
    const int ua   = lt & 63;             // act-phase unit 0..63
    const int b    = s * SPB + ba;        // global batch in group
    const int barid = 1 + s;
    const unsigned mb = smem_u32(&mbar[0]);
#define MBAR(ss, ii) (mb + (unsigned)(((ss) * 4 + (ii)) * 8))

    if (tid == 0) {
        #pragma unroll
        for (int s2 = 0; s2 < 2; ++s2) {
            if (rank < 2) {
                mbar_init(MBAR(s2, 0), 1); mbar_init(MBAR(s2, 1), 1);
                mbar_init(MBAR(s2, 2), 2); mbar_init(MBAR(s2, 3), 2);
            } else {
                mbar_init(MBAR(s2, 0), 2); mbar_init(MBAR(s2, 1), 2);
                mbar_init(MBAR(s2, 2), 1); mbar_init(MBAR(s2, 3), 1);
            }
        }
    }

    if (rank < 2) {
        // ===================== L0 half-CTA =====================
        const int half = rank;
        const unsigned peer = rank ^ 1u;
        {   // all 48 kb of L0 weights -> smem (both streams cooperate)
            const ulonglong2* src = (const ulonglong2*)g_W0B + (size_t)half * NB0 * RPC;
            for (int e = tid; e < NB0 * RPC; e += NTHR) ws[e] = ldcg_u2(src + e);
        }
        const int gr0 = half * UPC + ua;
        const float bi = b_ih0[gr0]        + b_hh0[gr0];
        const float bf = b_ih0[HH+gr0]     + b_hh0[HH+gr0];
        const float bg = b_ih0[2*HH+gr0]   + b_hh0[2*HH+gr0];
        const float bo = b_ih0[3*HH+gr0]   + b_hh0[3*HH+gr0];
        ubuf[0][b][DIN + ua]      = 0.0f;   // h0(-1) = 0, both halves
        ubuf[0][b][DIN + 64 + ua] = 0.0f;
        ubuf[0][b][ua] = ldcg(state + (gb + b) * DIN + ua);   // x(0)
        float cst = 0.0f;
        int pf[2] = {0, 0}, pe[2] = {0, 0};
        __syncthreads();
        CLUSTER_SYNC();

        for (int t = 0; t < TT; ++t) {
            const int q = t & 1;
            float xr = 0.0f;
            if (t + 1 < TT)
                xr = ldcg(state + ((size_t)(t + 1) * BSZ + gb + b) * DIN + ua);
            if (lt == 0) {
                if (t > 0)  mbar_wait(MBAR(s, q),     (unsigned)pf[q]);
                if (t >= 2) mbar_wait(MBAR(s, 2 + q), (unsigned)pe[q]);
            }
            if (t > 0)  pf[q] ^= 1;
            if (t >= 2) pe[q] ^= 1;
            bar_s(barid);   // B1: slot q inputs complete
            ubuf[q ^ 1][b][ua] = xr;

            // ---- dot token: enforce s0(t) -> s1(t) -> s0(t+1) ordering ----
            if (s == 0) { if (t > 0) tok_wait(4); }
            else       { tok_wait(3); }

            {   // dot: 2 rows (rt, rt+128) x 4 batches, kb = seg*24 .. +24
                unsigned long long acc[8];
                #pragma unroll
                for (int i = 0; i < 8; ++i) acc[i] = 0ull;
                const float* xb = &ubuf[q][s * SPB][0];
                const int kb0 = seg * 24;
                #pragma unroll 4
                for (int kb = 0; kb < 24; ++kb) {
                    const int kk = kb0 + kb;
                    ulonglong2 w0 = ws[(size_t)kk * RPC + rt];
                    ulonglong2 w1 = ws[(size_t)kk * RPC + rt + 128];
                    #pragma unroll
                    for (int bl = 0; bl < SPB; ++bl) {
                        ulonglong2 xv = ((const ulonglong2*)(xb + (size_t)bl * 256))[kk];
                        fma2(acc[bl],     w0.x, xv.x); fma2(acc[bl],     w0.y, xv.y);
                        fma2(acc[4 + bl], w1.x, xv.x); fma2(acc[4 + bl], w1.y, xv.y);
                    }
                }
                #pragma unroll
                for (int bl = 0; bl < SPB; ++bl) {
                    sg[s][bl][seg][rt]       = flo(acc[bl])     + fhi(acc[bl]);
                    sg[s][bl][seg][rt + 128] = flo(acc[4 + bl]) + fhi(acc[4 + bl]);
                }
            }
            // release port token to the other stream
            if (s == 0) tok_arrive(3); else tok_arrive(4);
            bar_s(barid);   // B2

            {   // act
                float p0 = sg[s][ba][0][ua]      + sg[s][ba][1][ua]      + bi;
                float p1 = sg[s][ba][0][64+ua]   + sg[s][ba][1][64+ua]   + bf;
                float p2 = sg[s][ba][0][128+ua]  + sg[s][ba][1][128+ua]  + bg;
                float p3 = sg[s][ba][0][192+ua]  + sg[s][ba][1][192+ua]  + bo;
                float gi = sigf(p0), gf = sigf(p1);
                float gG = tanhfast(p2), go = sigf(p3);
                cst = gf * cst + gi * gG;
                float h = go * tanhfast(cst);
                float* lp = &ubuf[q ^ 1][b][DIN + gr0];
                *lp = h;                                     // own recurrence
                st_dsmem(smem_u32(lp), peer, h);             // peer L0, same offset
                unsigned l1a = smem_u32(&ubuf[q][b][gr0]);   // L1 h0 region
                st_dsmem(l1a, 2u, h);
                st_dsmem(l1a, 3u, h);
            }
            bar_s(barid);   // B3
            if (lt == 0) {
                mbar_arrive_rk(MBAR(s, q ^ 1), peer);   // peer F[q^1]
                mbar_arrive_rk(MBAR(s, q), 2u);         // L1a H[q]
                mbar_arrive_rk(MBAR(s, q), 3u);         // L1b H[q]
            }
        }
        CLUSTER_SYNC();
    } else {
        // ===================== L1 half-CTA =====================
        const int half = rank - 2;
        const unsigned peer_rk = rank ^ 1u;
        {   // kb 0..47 of L1 weights -> smem; tail 48..63 stays in gmem (L2)
            const ulonglong2* src = (const ulonglong2*)g_W1B + (size_t)half * NB1 * RPC;
            for (int e = tid; e < SKB1 * RPC; e += NTHR) ws[e] = ldcg_u2(src + e);
        }
        const ulonglong2* wg = (const ulonglong2*)g_W1B
                             + ((size_t)half * NB1 + 48) * RPC;   // kb 48..63
        const int gr0 = half * UPC + ua;
        const float bi = b_ih1[gr0]        + b_hh1[gr0];
        const float bf = b_ih1[HH+gr0]     + b_hh1[HH+gr0];
        const float bg = b_ih1[2*HH+gr0]   + b_hh1[2*HH+gr0];
        const float bo = b_ih1[3*HH+gr0]   + b_hh1[3*HH+gr0];
        if (rank == 2) {
            if (tid < HH) swout[tid] = W_out[tid];
            if (tid == 0) sbout = b_out[0];
        }
        ubuf[0][b][HH + ua]      = 0.0f;   // h1(-1) = 0, both halves
        ubuf[0][b][HH + 64 + ua] = 0.0f;
        float cst = 0.0f;
        int ph[2] = {0, 0}, pqf[2] = {0, 0};
        __syncthreads();
        CLUSTER_SYNC();

        for (int t = 0; t < TT; ++t) {
            const int q = t & 1;
            if (lt == 0) {
                mbar_wait(MBAR(s, q), (unsigned)ph[q]);                   // h0(t)
                if (t > 0) mbar_wait(MBAR(s, 2 + q), (unsigned)pqf[q]);   // peer h1(t-1)
            }
            ph[q] ^= 1;
            if (t > 0) pqf[q] ^= 1;
            bar_s(barid);   // B1: slot q = [h0(t) | h1(t-1)] complete

            // head: out(t-1) for this stream's 4 batches (rank2 only)
            if (rank == 2 && t > 0 && lt < 32) {
                int bl = lt >> 3, ch = lt & 7;
                const float* hv = &ubuf[q][s * SPB + bl][HH];
                float p = 0.0f;
                #pragma unroll
                for (int m = 0; m < 16; ++m) {
                    int u = ch * 16 + m;
                    p += hv[u] * swout[u];
                }
                p += __shfl_down_sync(0xffffffffu, p, 4, 8);
                p += __shfl_down_sync(0xffffffffu, p, 2, 8);
                p += __shfl_down_sync(0xffffffffu, p, 1, 8);
                if (ch == 0)
                    out[(size_t)(t - 1) * BSZ + gb + s * SPB + bl] = p + sbout;
            }

            // ---- dot token ----
            if (s == 0) { if (t > 0) tok_wait(4); }
            else       { tok_wait(3); }

            {   // dot: 2 rows x 4 batches over 32 kb
                // seg0: kb 0..31 smem; seg1: gmem tail FIRST (MLP), then smem
                unsigned long long acc[8];
                #pragma unroll
                for (int i = 0; i < 8; ++i) acc[i] = 0ull;
                const float* xb = &ubuf[q][s * SPB][0];
                if (seg == 0) {
                    #pragma unroll 4
                    for (int kk = 0; kk < 32; ++kk) {
                        ulonglong2 w0 = ws[(size_t)kk * RPC + rt];
                        ulonglong2 w1 = ws[(size_t)kk * RPC + rt + 128];
                        #pragma unroll
                        for (int bl = 0; bl < SPB; ++bl) {
                            ulonglong2 xv = ((const ulonglong2*)(xb + (size_t)bl * 256))[kk];
                            fma2(acc[bl],     w0.x, xv.x); fma2(acc[bl],     w0.y, xv.y);
                            fma2(acc[4 + bl], w1.x, xv.x); fma2(acc[4 + bl], w1.y, xv.y);
                        }
                    }
                } else {
                    #pragma unroll 4
                    for (int kt = 0; kt < 16; ++kt) {   // L2 tail first: deep MLP
                        const int kk = 48 + kt;
                        ulonglong2 w0 = ldcg_u2(wg + (size_t)kt * RPC + rt);
                        ulonglong2 w1 = ldcg_u2(wg + (size_t)kt * RPC + rt + 128);
                        #pragma unroll
                        for (int bl = 0; bl < SPB; ++bl) {
                            ulonglong2 xv = ((const ulonglong2*)(xb + (size_t)bl * 256))[kk];
                            fma2(acc[bl],     w0.x, xv.x); fma2(acc[bl],     w0.y, xv.y);
                            fma2(acc[4 + bl], w1.x, xv.x); fma2(acc[4 + bl], w1.y, xv.y);
                        }
                    }
                    #pragma unroll 4
                    for (int kk = 32; kk < 48; ++kk) {
                        ulonglong2 w0 = ws[(size_t)kk * RPC + rt];
                        ulonglong2 w1 = ws[(size_t)kk * RPC + rt + 128];
                        #pragma unroll
                        for (int bl = 0; bl < SPB; ++bl) {
                            ulonglong2 xv = ((const ulonglong2*)(xb + (size_t)bl * 256))[kk];
                            fma2(acc[bl],     w0.x, xv.x); fma2(acc[bl],     w0.y, xv.y);
                            fma2(acc[4 + bl], w1.x, xv.x); fma2(acc[4 + bl], w1.y, xv.y);
                        }
                    }
                }
                #pragma unroll
                for (int bl = 0; bl < SPB; ++bl) {
                    sg[s][bl][seg][rt]       = flo(acc[bl])     + fhi(acc[bl]);
                    sg[s][bl][seg][rt + 128] = flo(acc[4 + bl]) + fhi(acc[4 + bl]);
                }
            }
            if (s == 0) tok_arrive(3); else tok_arrive(4);
            bar_s(barid);   // B2: slot-q reads done
            if (lt == 0) {   // release h0 slot q to both L0 CTAs
                mbar_arrive_rk(MBAR(s, 2 + q), 0u);
                mbar_arrive_rk(MBAR(s, 2 + q), 1u);
            }

            {   // act
                float p0 = sg[s][ba][0][ua]      + sg[s][ba][1][ua]      + bi;
                float p1 = sg[s][ba][0][64+ua]   + sg[s][ba][1][64+ua]   + bf;
                float p2 = sg[s][ba][0][128+ua]  + sg[s][ba][1][128+ua]  + bg;
                float p3 = sg[s][ba][0][192+ua]  + sg[s][ba][1][192+ua]  + bo;
                float gi = sigf(p0), gf = sigf(p1);
                float gG = tanhfast(p2), go = sigf(p3);
                cst = gf * cst + gi * gG;
                float h = go * tanhfast(cst);
                float* lp = &ubuf[q ^ 1][b][HH + gr0];
                *lp = h;                                  // own recurrence
                st_dsmem(smem_u32(lp), peer_rk, h);       // peer L1, same offset
            }
            bar_s(barid);   // B3
            if (lt == 0)
                mbar_arrive_rk(MBAR(s, 2 + (q ^ 1)), peer_rk);   // peer Q[q^1]
        }

        // epilogue: out(TT-1) per stream (rank2)
        if (rank == 2 && lt < 32) {
            mbar_wait(MBAR(s, 2 + 0), (unsigned)pqf[0]);   // peer h1(TT-1), slot 0
            int bl = lt >> 3, ch = lt & 7;
            const float* hv = &ubuf[0][s * SPB + bl][HH];
            float p = 0.0f;
            #pragma unroll
            for (int m = 0; m < 16; ++m) {
                int u = ch * 16 + m;
                p += hv[u] * swout[u];
            }
            p += __shfl_down_sync(0xffffffffu, p, 4, 8);
            p += __shfl_down_sync(0xffffffffu, p, 2, 8);
            p += __shfl_down_sync(0xffffffffu, p, 1, 8);
            if (ch == 0)
                out[(size_t)(TT - 1) * BSZ + gb + s * SPB + bl] = p + sbout;
        }
        CLUSTER_SYNC();
    }
#undef MBAR
}

extern "C" void kernel_launch(void* const* d_in, const int* in_sizes, int n_in,
                              void* d_out, int out_size)
{
    const float* state = (const float*)d_in[0];
    const float* W_ih0 = (const float*)d_in[1];
    const float* W_hh0 = (const float*)d_in[2];
    const float* b_ih0 = (const float*)d_in[3];
    const float* b_hh0 = (const float*)d_in[4];
    const float* W_ih1 = (const float*)d_in[5];
    const float* W_hh1 = (const float*)d_in[6];
    const float* b_ih1 = (const float*)d_in[7];
    const float* b_hh1 = (const float*)d_in[8];
    const float* W_out = (const float*)d_in[9];
    const float* b_out = (const float*)d_in[10];
    float* out = (float*)d_out;

    cudaFuncSetAttribute(lstm_kernel,
                         cudaFuncAttributeMaxDynamicSharedMemorySize, DYNSMEM);
    prep_kernel<<<224, 512>>>(W_ih0, W_hh0, W_ih1, W_hh1);
    lstm_kernel<<<NCTA, NTHR, DYNSMEM>>>(state, b_ih0, b_hh0, b_ih1, b_hh1,
                                         W_out, b_out, out);
}

// round 17
// speedup vs baseline: 1.5242x; 1.0498x over previous
#include <cuda_runtime.h>

#define TT    512
#define BSZ   256
#define DIN   64
#define HH    128
#define BPC   8
#define SPB   4          // batches per stream
#define NGRP  32
#define NTHR  512
#define RPC   256        // rows per CTA: 4 gates x 64 units
#define UPC   64
#define NB0   48         // k-blocks layer0 (K=192)
#define NB1   64         // k-blocks layer1 (K=256)
#define SKB1  48         // smem-resident kb (layer1)
#define NCTA  (NGRP*4)   // 128
#define DYNSMEM (48*RPC*16)   // 192 KB

// Blocked weights: [(half*NB + kb)*RPC + r] float4 = W[grow][4kb..4kb+3]
__device__ float4 g_W0B[2 * NB0 * RPC];
__device__ float4 g_W1B[2 * NB1 * RPC];

__global__ void prep_kernel(const float* __restrict__ Wih0,
                            const float* __restrict__ Whh0,
                            const float* __restrict__ Wih1,
                            const float* __restrict__ Whh1)
{
    int idx = blockIdx.x * blockDim.x + threadIdx.x;
    int stride = gridDim.x * blockDim.x;
    for (int e = idx; e < 2 * NB0 * RPC * 4; e += stride) {
        int i = e & 3, e2 = e >> 2;
        int r = e2 % RPC, e3 = e2 / RPC;
        int kb = e3 % NB0, half = e3 / NB0;
        int k = kb * 4 + i;
        int gate = r >> 6, ul = r & 63;
        int grow = gate * HH + half * UPC + ul;
        float v = (k < DIN) ? Wih0[grow * DIN + k] : Whh0[grow * HH + (k - DIN)];
        ((float*)g_W0B)[e] = v;
    }
    for (int e = idx; e < 2 * NB1 * RPC * 4; e += stride) {
        int i = e & 3, e2 = e >> 2;
        int r = e2 % RPC, e3 = e2 / RPC;
        int kb = e3 % NB1, half = e3 / NB1;
        int k = kb * 4 + i;
        int gate = r >> 6, ul = r & 63;
        int grow = gate * HH + half * UPC + ul;
        float v = (k < HH) ? Wih1[grow * HH + k] : Whh1[grow * HH + (k - HH)];
        ((float*)g_W1B)[e] = v;
    }
}

__device__ __forceinline__ void fma2(unsigned long long& d,
                                     unsigned long long a,
                                     unsigned long long b)
{
    asm("fma.rn.f32x2 %0, %1, %2, %0;" : "+l"(d) : "l"(a), "l"(b));
}
__device__ __forceinline__ float flo(unsigned long long v) {
    return __uint_as_float((unsigned)(v & 0xffffffffu));
}
__device__ __forceinline__ float fhi(unsigned long long v) {
    return __uint_as_float((unsigned)(v >> 32));
}
__device__ __forceinline__ float sigf(float x) {
    return __fdividef(1.0f, 1.0f + __expf(-x));
}
__device__ __forceinline__ float tanhfast(float x) {
    return 1.0f - __fdividef(2.0f, __expf(2.0f * x) + 1.0f);
}
__device__ __forceinline__ float ldcg(const float* p) {
    float v;
    asm volatile("ld.global.cg.f32 %0, [%1];" : "=f"(v) : "l"(p) : "memory");
    return v;
}
__device__ __forceinline__ ulonglong2 ldcg_u2(const ulonglong2* p) {
    ulonglong2 v;
    asm volatile("ld.global.cg.v2.u64 {%0,%1}, [%2];"
                 : "=l"(v.x), "=l"(v.y) : "l"(p) : "memory");
    return v;
}
__device__ __forceinline__ unsigned smem_u32(const void* p) {
    unsigned a;
    asm("{ .reg .u64 t; cvta.to.shared.u64 t, %1; cvt.u32.u64 %0, t; }"
        : "=r"(a) : "l"(p));
    return a;
}
__device__ __forceinline__ unsigned cta_rank() {
    unsigned r;
    asm("mov.u32 %0, %%cluster_ctarank;" : "=r"(r));
    return r;
}
__device__ __forceinline__ unsigned mapa_u32(unsigned a, unsigned rank) {
    unsigned r;
    asm("mapa.shared::cluster.u32 %0, %1, %2;" : "=r"(r) : "r"(a), "r"(rank));
    return r;
}
__device__ __forceinline__ void mbar_init(unsigned a, unsigned cnt) {
    asm volatile("mbarrier.init.shared.b64 [%0], %1;" :: "r"(a), "r"(cnt) : "memory");
}
__device__ __forceinline__ void mbar_arrive_rk(unsigned local_a, unsigned rank) {
    unsigned ra = mapa_u32(local_a, rank);
    asm volatile("mbarrier.arrive.release.cluster.shared::cluster.b64 _, [%0];"
                 :: "r"(ra) : "memory");
}
__device__ __forceinline__ void mbar_wait(unsigned a, unsigned parity) {
    asm volatile(
        "{\n\t.reg .pred P;\n\t"
        "W_%=:\n\t"
        "mbarrier.try_wait.parity.acquire.cluster.shared::cta.b64 P, [%0], %1, 0x989680;\n\t"
        "@P bra D_%=;\n\t"
        "bra W_%=;\n\t"
        "D_%=:\n\t}"
        :: "r"(a), "r"(parity) : "memory");
}
__device__ __forceinline__ void st_dsmem(unsigned local_a, unsigned rank, float v) {
    unsigned ra = mapa_u32(local_a, rank);
    asm volatile("st.shared::cluster.f32 [%0], %1;" :: "r"(ra), "f"(v) : "memory");
}
__device__ __forceinline__ void bar_s(int id) {
    asm volatile("bar.sync %0, %1;" :: "r"(id), "r"(256) : "memory");
}
__device__ __forceinline__ void tok_arrive(int id) {
    asm volatile("bar.arrive %0, %1;" :: "r"(id), "r"(512) : "memory");
}
__device__ __forceinline__ void tok_wait(int id) {
    asm volatile("bar.sync %0, %1;" :: "r"(id), "r"(512) : "memory");
}
#define CLUSTER_SYNC() do { \
    asm volatile("barrier.cluster.arrive.aligned;" ::: "memory"); \
    asm volatile("barrier.cluster.wait.aligned;" ::: "memory"); \
} while (0)

__global__ void __launch_bounds__(NTHR, 1) __cluster_dims__(4, 1, 1)
lstm_kernel(const float* __restrict__ state,
            const float* __restrict__ b_ih0, const float* __restrict__ b_hh0,
            const float* __restrict__ b_ih1, const float* __restrict__ b_hh1,
            const float* __restrict__ W_out, const float* __restrict__ b_out,
            float* __restrict__ out)
{
    extern __shared__ __align__(16) ulonglong2 ws[];   // resident weights (48 kb)

    __shared__ __align__(16) float ubuf[2][BPC][256];
    __shared__ float sg[2][SPB][2][RPC];   // [stream][batch][seg][row]
    __shared__ float swout[HH];
    __shared__ float sbout;
    __shared__ __align__(8) unsigned long long mbar[8];
    // L0: idx 0/1 = F[q] peer-h0 full (cnt1); idx 2/3 = E[q] L1-consumed (cnt2)
    // L1: idx 0/1 = H[q] h0 full (cnt2);     idx 2/3 = Q[q] peer-h1 full (cnt1)

    const int grp  = blockIdx.x >> 2;
    const int gb   = grp * BPC;
    const unsigned rank = cta_rank();
    const int tid  = threadIdx.x;
    const int s    = tid >> 8;            // stream 0/1
    const int lt   = tid & 255;
    const int seg  = lt >> 7;             // k-segment (dot phase)
    const int rt   = lt & 127;            // rows rt, rt+128
    const int ba   = lt >> 6;             // act-phase local batch 0..3
    const int ua   = lt & 63;
    const int b    = s * SPB + ba;
    const int barid = 1 + s;
    const unsigned mb = smem_u32(&mbar[0]);
#define MBAR(ss, ii) (mb + (unsigned)(((ss) * 4 + (ii)) * 8))

    if (tid == 0) {
        #pragma unroll
        for (int s2 = 0; s2 < 2; ++s2) {
            if (rank < 2) {
                mbar_init(MBAR(s2, 0), 1); mbar_init(MBAR(s2, 1), 1);
                mbar_init(MBAR(s2, 2), 2); mbar_init(MBAR(s2, 3), 2);
            } else {
                mbar_init(MBAR(s2, 0), 2); mbar_init(MBAR(s2, 1), 2);
                mbar_init(MBAR(s2, 2), 1); mbar_init(MBAR(s2, 3), 1);
            }
        }
    }

    if (rank < 2) {
        // ===================== L0 half-CTA =====================
        const int half = rank;
        const unsigned peer = rank ^ 1u;
        {   // all 48 kb -> smem
            const ulonglong2* src = (const ulonglong2*)g_W0B + (size_t)half * NB0 * RPC;
            for (int e = tid; e < NB0 * RPC; e += NTHR) ws[e] = ldcg_u2(src + e);
        }
        // register-resident kb: seg's last 8 (kb seg*24+16 .. +23)
        ulonglong2 wrA[8], wrB[8];
        {
            const ulonglong2* gsrc = (const ulonglong2*)g_W0B
                + ((size_t)half * NB0 + (size_t)(seg * 24 + 16)) * RPC;
            #pragma unroll
            for (int j = 0; j < 8; ++j) {
                wrA[j] = ldcg_u2(gsrc + (size_t)j * RPC + rt);
                wrB[j] = ldcg_u2(gsrc + (size_t)j * RPC + rt + 128);
            }
        }
        const int gr0 = half * UPC + ua;
        const float bi = b_ih0[gr0]        + b_hh0[gr0];
        const float bf = b_ih0[HH+gr0]     + b_hh0[HH+gr0];
        const float bg = b_ih0[2*HH+gr0]   + b_hh0[2*HH+gr0];
        const float bo = b_ih0[3*HH+gr0]   + b_hh0[3*HH+gr0];
        ubuf[0][b][DIN + ua]      = 0.0f;
        ubuf[0][b][DIN + 64 + ua] = 0.0f;
        ubuf[0][b][ua] = ldcg(state + (gb + b) * DIN + ua);   // x(0)
        float cst = 0.0f;
        int pf[2] = {0, 0}, pe[2] = {0, 0};
        __syncthreads();
        CLUSTER_SYNC();

        for (int t = 0; t < TT; ++t) {
            const int q = t & 1;
            float xr = 0.0f;
            if (t + 1 < TT)
                xr = ldcg(state + ((size_t)(t + 1) * BSZ + gb + b) * DIN + ua);
            if (lt == 0) {
                if (t > 0)  mbar_wait(MBAR(s, q),     (unsigned)pf[q]);
                if (t >= 2) mbar_wait(MBAR(s, 2 + q), (unsigned)pe[q]);
            }
            if (t > 0)  pf[q] ^= 1;
            if (t >= 2) pe[q] ^= 1;
            bar_s(barid);   // B1
            ubuf[q ^ 1][b][ua] = xr;

            if (s == 0) { if (t > 0) tok_wait(4); }
            else       { tok_wait(3); }

            {   // dot: 16 kb smem + 8 kb regs
                unsigned long long acc[8];
                #pragma unroll
                for (int i = 0; i < 8; ++i) acc[i] = 0ull;
                const float* xb = &ubuf[q][s * SPB][0];
                const int kb0 = seg * 24;
                #pragma unroll 4
                for (int kb = 0; kb < 16; ++kb) {
                    const int kk = kb0 + kb;
                    ulonglong2 w0 = ws[(size_t)kk * RPC + rt];
                    ulonglong2 w1 = ws[(size_t)kk * RPC + rt + 128];
                    #pragma unroll
                    for (int bl = 0; bl < SPB; ++bl) {
                        ulonglong2 xv = ((const ulonglong2*)(xb + (size_t)bl * 256))[kk];
                        fma2(acc[bl],     w0.x, xv.x); fma2(acc[bl],     w0.y, xv.y);
                        fma2(acc[4 + bl], w1.x, xv.x); fma2(acc[4 + bl], w1.y, xv.y);
                    }
                }
                #pragma unroll
                for (int j = 0; j < 8; ++j) {
                    const int kk = kb0 + 16 + j;
                    #pragma unroll
                    for (int bl = 0; bl < SPB; ++bl) {
                        ulonglong2 xv = ((const ulonglong2*)(xb + (size_t)bl * 256))[kk];
                        fma2(acc[bl],     wrA[j].x, xv.x); fma2(acc[bl],     wrA[j].y, xv.y);
                        fma2(acc[4 + bl], wrB[j].x, xv.x); fma2(acc[4 + bl], wrB[j].y, xv.y);
                    }
                }
                #pragma unroll
                for (int bl = 0; bl < SPB; ++bl) {
                    sg[s][bl][seg][rt]       = flo(acc[bl])     + fhi(acc[bl]);
                    sg[s][bl][seg][rt + 128] = flo(acc[4 + bl]) + fhi(acc[4 + bl]);
                }
            }
            if (s == 0) tok_arrive(3); else tok_arrive(4);
            bar_s(barid);   // B2

            {   // act
                float p0 = sg[s][ba][0][ua]      + sg[s][ba][1][ua]      + bi;
                float p1 = sg[s][ba][0][64+ua]   + sg[s][ba][1][64+ua]   + bf;
                float p2 = sg[s][ba][0][128+ua]  + sg[s][ba][1][128+ua]  + bg;
                float p3 = sg[s][ba][0][192+ua]  + sg[s][ba][1][192+ua]  + bo;
                float gi = sigf(p0), gf = sigf(p1);
                float gG = tanhfast(p2), go = sigf(p3);
                cst = gf * cst + gi * gG;
                float h = go * tanhfast(cst);
                float* lp = &ubuf[q ^ 1][b][DIN + gr0];
                *lp = h;
                st_dsmem(smem_u32(lp), peer, h);
                unsigned l1a = smem_u32(&ubuf[q][b][gr0]);
                st_dsmem(l1a, 2u, h);
                st_dsmem(l1a, 3u, h);
            }
            bar_s(barid);   // B3
            if (lt == 0) {
                mbar_arrive_rk(MBAR(s, q ^ 1), peer);
                mbar_arrive_rk(MBAR(s, q), 2u);
                mbar_arrive_rk(MBAR(s, q), 3u);
            }
        }
        CLUSTER_SYNC();
    } else {
        // ===================== L1 half-CTA =====================
        const int half = rank - 2;
        const unsigned peer_rk = rank ^ 1u;
        {   // smem: kb 0..23 -> ws[0..24), kb 32..55 -> ws[24..48)
            const ulonglong2* src = (const ulonglong2*)g_W1B + (size_t)half * NB1 * RPC;
            for (int e = tid; e < SKB1 * RPC; e += NTHR) {
                int idx = e >> 8, rr = e & 255;
                int kbn = (idx < 24) ? idx : (idx + 8);
                ws[e] = ldcg_u2(src + ((size_t)kbn * RPC + rr));
            }
        }
        // register-resident kb: seg0 -> 24..31, seg1 -> 56..63
        ulonglong2 wrA[8], wrB[8];
        {
            const int kb0r = seg ? 56 : 24;
            const ulonglong2* gsrc = (const ulonglong2*)g_W1B
                + ((size_t)half * NB1 + (size_t)kb0r) * RPC;
            #pragma unroll
            for (int j = 0; j < 8; ++j) {
                wrA[j] = ldcg_u2(gsrc + (size_t)j * RPC + rt);
                wrB[j] = ldcg_u2(gsrc + (size_t)j * RPC + rt + 128);
            }
        }
        const int gr0 = half * UPC + ua;
        const float bi = b_ih1[gr0]        + b_hh1[gr0];
        const float bf = b_ih1[HH+gr0]     + b_hh1[HH+gr0];
        const float bg = b_ih1[2*HH+gr0]   + b_hh1[2*HH+gr0];
        const float bo = b_ih1[3*HH+gr0]   + b_hh1[3*HH+gr0];
        if (rank == 2) {
            if (tid < HH) swout[tid] = W_out[tid];
            if (tid == 0) sbout = b_out[0];
        }
        ubuf[0][b][HH + ua]      = 0.0f;
        ubuf[0][b][HH + 64 + ua] = 0.0f;
        float cst = 0.0f;
        int ph[2] = {0, 0}, pqf[2] = {0, 0};
        __syncthreads();
        CLUSTER_SYNC();

        for (int t = 0; t < TT; ++t) {
            const int q = t & 1;
            if (lt == 0) {
                mbar_wait(MBAR(s, q), (unsigned)ph[q]);
                if (t > 0) mbar_wait(MBAR(s, 2 + q), (unsigned)pqf[q]);
            }
            ph[q] ^= 1;
            if (t > 0) pqf[q] ^= 1;
            bar_s(barid);   // B1

            // head: out(t-1) for this stream's 4 batches (rank2 only)
            if (rank == 2 && t > 0 && lt < 32) {
                int bl = lt >> 3, ch = lt & 7;
                const float* hv = &ubuf[q][s * SPB + bl][HH];
                float p = 0.0f;
                #pragma unroll
                for (int m = 0; m < 16; ++m) {
                    int u = ch * 16 + m;
                    p += hv[u] * swout[u];
                }
                p += __shfl_down_sync(0xffffffffu, p, 4, 8);
                p += __shfl_down_sync(0xffffffffu, p, 2, 8);
                p += __shfl_down_sync(0xffffffffu, p, 1, 8);
                if (ch == 0)
                    out[(size_t)(t - 1) * BSZ + gb + s * SPB + bl] = p + sbout;
            }

            if (s == 0) { if (t > 0) tok_wait(4); }
            else       { tok_wait(3); }

            {   // dot: 24 kb smem + 8 kb regs (seg0: 0..31, seg1: 32..63)
                unsigned long long acc[8];
                #pragma unroll
                for (int i = 0; i < 8; ++i) acc[i] = 0ull;
                const float* xb = &ubuf[q][s * SPB][0];
                const int kbase = seg ? 32 : 0;
                const int wsadj = seg ? -8 : 0;
                #pragma unroll 4
                for (int kb = 0; kb < 24; ++kb) {
                    const int kk = kbase + kb;
                    ulonglong2 w0 = ws[(size_t)(kk + wsadj) * RPC + rt];
                    ulonglong2 w1 = ws[(size_t)(kk + wsadj) * RPC + rt + 128];
                    #pragma unroll
                    for (int bl = 0; bl < SPB; ++bl) {
                        ulonglong2 xv = ((const ulonglong2*)(xb + (size_t)bl * 256))[kk];
                        fma2(acc[bl],     w0.x, xv.x); fma2(acc[bl],     w0.y, xv.y);
                        fma2(acc[4 + bl], w1.x, xv.x); fma2(acc[4 + bl], w1.y, xv.y);
                    }
                }
                #pragma unroll
                for (int j = 0; j < 8; ++j) {
                    const int kk = kbase + 24 + j;
                    #pragma unroll
                    for (int bl = 0; bl < SPB; ++bl) {
                        ulonglong2 xv = ((const ulonglong2*)(xb + (size_t)bl * 256))[kk];
                        fma2(acc[bl],     wrA[j].x, xv.x); fma2(acc[bl],     wrA[j].y, xv.y);
                        fma2(acc[4 + bl], wrB[j].x, xv.x); fma2(acc[4 + bl], wrB[j].y, xv.y);
                    }
                }
                #pragma unroll
                for (int bl = 0; bl < SPB; ++bl) {
                    sg[s][bl][seg][rt]       = flo(acc[bl])     + fhi(acc[bl]);
                    sg[s][bl][seg][rt + 128] = flo(acc[4 + bl]) + fhi(acc[4 + bl]);
                }
            }
            if (s == 0) tok_arrive(3); else tok_arrive(4);
            bar_s(barid);   // B2
            if (lt == 0) {
                mbar_arrive_rk(MBAR(s, 2 + q), 0u);
                mbar_arrive_rk(MBAR(s, 2 + q), 1u);
            }

            {   // act
                float p0 = sg[s][ba][0][ua]      + sg[s][ba][1][ua]      + bi;
                float p1 = sg[s][ba][0][64+ua]   + sg[s][ba][1][64+ua]   + bf;
                float p2 = sg[s][ba][0][128+ua]  + sg[s][ba][1][128+ua]  + bg;
                float p3 = sg[s][ba][0][192+ua]  + sg[s][ba][1][192+ua]  + bo;
                float gi = sigf(p0), gf = sigf(p1);
                float gG = tanhfast(p2), go = sigf(p3);
                cst = gf * cst + gi * gG;
                float h = go * tanhfast(cst);
                float* lp = &ubuf[q ^ 1][b][HH + gr0];
                *lp = h;
                st_dsmem(smem_u32(lp), peer_rk, h);
            }
            bar_s(barid);   // B3
            if (lt == 0)
                mbar_arrive_rk(MBAR(s, 2 + (q ^ 1)), peer_rk);
        }

        // epilogue: out(TT-1) per stream (rank2)
        if (rank == 2 && lt < 32) {
            mbar_wait(MBAR(s, 2 + 0), (unsigned)pqf[0]);
            int bl = lt >> 3, ch = lt & 7;
            const float* hv = &ubuf[0][s * SPB + bl][HH];
            float p = 0.0f;
            #pragma unroll
            for (int m = 0; m < 16; ++m) {
                int u = ch * 16 + m;
                p += hv[u] * swout[u];
            }
            p += __shfl_down_sync(0xffffffffu, p, 4, 8);
            p += __shfl_down_sync(0xffffffffu, p, 2, 8);
            p += __shfl_down_sync(0xffffffffu, p, 1, 8);
            if (ch == 0)
                out[(size_t)(TT - 1) * BSZ + gb + s * SPB + bl] = p + sbout;
        }
        CLUSTER_SYNC();
    }
#undef MBAR
}

extern "C" void kernel_launch(void* const* d_in, const int* in_sizes, int n_in,
                              void* d_out, int out_size)
{
    const float* state = (const float*)d_in[0];
    const float* W_ih0 = (const float*)d_in[1];
    const float* W_hh0 = (const float*)d_in[2];
    const float* b_ih0 = (const float*)d_in[3];
    const float* b_hh0 = (const float*)d_in[4];
    const float* W_ih1 = (const float*)d_in[5];
    const float* W_hh1 = (const float*)d_in[6];
    const float* b_ih1 = (const float*)d_in[7];
    const float* b_hh1 = (const float*)d_in[8];
    const float* W_out = (const float*)d_in[9];
    const float* b_out = (const float*)d_in[10];
    float* out = (float*)d_out;

    cudaFuncSetAttribute(lstm_kernel,
                         cudaFuncAttributeMaxDynamicSharedMemorySize, DYNSMEM);
    prep_kernel<<<224, 512>>>(W_ih0, W_hh0, W_ih1, W_hh1);
    lstm_kernel<<<NCTA, NTHR, DYNSMEM>>>(state, b_ih0, b_hh0, b_ih1, b_hh1,
                                         W_out, b_out, out);
}